// round 9
// baseline (speedup 1.0000x reference)
#include <cuda_runtime.h>
#include <cstdint>
#include <math.h>
#include <float.h>

#define BD 2
#define TT 2048
#define DDIM 2048
#define NH 16
#define HD 128
#define BH (BD*NH)         // 32
#define MROWS (BD*TT)      // 4096
#define E3 (3*DDIM)        // 6144
#define SCALE 0.08838834764831843f

// CTA tile 256x128, K-chunk 16, row pitch 80B (conflict-free ldmatrix)
#define TM 256
#define TN 128
#define PITCH 80
#define ASZ (TM*PITCH)     // 20480
#define BSZ (TN*PITCH)     // 10240
#define STG (ASZ+BSZ)      // 30720
#define SMEM_ALL (4*STG)   // 122880 (also covers 67584B qkv epilogue staging)

// ------------------ scratch (static device, allocation-free) ------------------
__device__ float g_x [(size_t)MROWS*DDIM];    // tf32-rounded X
__device__ float g_w [(size_t)E3*DDIM];       // tf32-rounded qkv_w
__device__ float g_wo[(size_t)DDIM*DDIM];     // tf32-rounded out_w
__device__ float g_q[(size_t)BH*TT*HD];       // tf32-rounded (RoPE'd)
__device__ float g_k[(size_t)BH*TT*HD];
__device__ float g_vt[(size_t)BH*HD*TT];      // V transposed [bh][d][t], tf32-rounded
__device__ float g_s[(size_t)BH*TT*TT];       // raw scaled scores (fp32)
__device__ float g_attn[(size_t)MROWS*DDIM];  // tf32-rounded

// ------------------ helpers ------------------
static __device__ __forceinline__ uint32_t smem_u32(const void* p){
    uint32_t a;
    asm("{ .reg .u64 t; cvta.to.shared.u64 t, %1; cvt.u32.u64 %0, t; }" : "=r"(a) : "l"(p));
    return a;
}
static __device__ __forceinline__ uint32_t f2tf32(float x){
    uint32_t y; asm("cvt.rn.tf32.f32 %0, %1;" : "=r"(y) : "f"(x)); return y;
}
static __device__ __forceinline__ float rnd(float x){ return __uint_as_float(f2tf32(x)); }

static __device__ __forceinline__ void cp16(uint32_t dst, const void* src){
    uint64_t g;
    asm("cvta.to.global.u64 %0, %1;" : "=l"(g) : "l"(src));
    asm volatile("cp.async.cg.shared.global [%0], [%1], 16;" :: "r"(dst), "l"(g) : "memory");
}
#define CP_COMMIT() asm volatile("cp.async.commit_group;" ::: "memory")
#define CP_WAIT2()  asm volatile("cp.async.wait_group 2;" ::: "memory")

#define LDMX4(r, addr) asm volatile( \
    "ldmatrix.sync.aligned.m8n8.x4.shared.b16 {%0,%1,%2,%3}, [%4];" \
    : "=r"((r)[0]),"=r"((r)[1]),"=r"((r)[2]),"=r"((r)[3]) : "r"(addr))

static __device__ __forceinline__ void mma8(float* c, const uint32_t* a, const uint32_t* b){
    asm volatile(
        "mma.sync.aligned.m16n8k8.row.col.f32.tf32.tf32.f32 "
        "{%0,%1,%2,%3}, {%4,%5,%6,%7}, {%8,%9}, {%0,%1,%2,%3};"
        : "+f"(c[0]), "+f"(c[1]), "+f"(c[2]), "+f"(c[3])
        : "r"(a[0]), "r"(a[1]), "r"(a[2]), "r"(a[3]), "r"(b[0]), "r"(b[1]));
}

// compute one K=16 chunk: warp tile 64x64, 64 MMAs
static __device__ __forceinline__ void compute16(uint32_t stg, float (&acc)[4][8][4],
                                                 int aoff, int boff)
{
    #pragma unroll
    for (int ks = 0; ks < 2; ks++){
        uint32_t a[4][4], b[4][4];
        #pragma unroll
        for (int mi = 0; mi < 4; mi++)
            LDMX4(a[mi], stg + aoff + mi*(16*PITCH) + ks*32);
        #pragma unroll
        for (int p = 0; p < 4; p++)
            LDMX4(b[p], stg + ASZ + boff + p*(16*PITCH) + ks*32);
        #pragma unroll
        for (int mi = 0; mi < 4; mi++)
            #pragma unroll
            for (int p = 0; p < 4; p++){
                mma8(acc[mi][2*p],   a[mi], &b[p][0]);
                mma8(acc[mi][2*p+1], a[mi], &b[p][2]);
            }
    }
}

// cp.async loads for one chunk (A: 256 rows, B: 128 rows)
static __device__ __forceinline__ void cp_issue(uint32_t stg,
    const float* __restrict__ A, size_t lda,
    const float* __restrict__ B, size_t ldb, int k0, int tid)
{
    const int rA = tid >> 2, kc = tid & 3;
    #pragma unroll
    for (int j = 0; j < 4; j++)
        cp16(stg + (rA + 64*j)*PITCH + kc*16, A + (size_t)(rA + 64*j)*lda + k0 + kc*4);
    const int rB = tid >> 1, kc2 = (tid & 1) * 2;
    #pragma unroll
    for (int j = 0; j < 2; j++)
        cp16(stg + ASZ + rB*PITCH + (kc2 + j)*16, B + (size_t)rB*ldb + k0 + (kc2 + j)*4);
}

// C[256,128] += A[256,K]*B[128,K]^T, K = nIter*16, 4-stage cp.async pipeline
static __device__ __forceinline__ void gemm_cp(uint32_t smb, float (&acc)[4][8][4],
    const float* __restrict__ A, size_t lda,
    const float* __restrict__ B, size_t ldb, int nIter, int aoff, int boff)
{
    const int tid = threadIdx.x;
    #pragma unroll
    for (int s = 0; s < 3; s++){
        if (s < nIter) cp_issue(smb + s*STG, A, lda, B, ldb, s*16, tid);
        CP_COMMIT();
    }
    for (int kt = 0; kt < nIter; kt++){
        CP_WAIT2();
        __syncthreads();
        if (kt + 3 < nIter) cp_issue(smb + ((kt+3)&3)*STG, A, lda, B, ldb, (kt+3)*16, tid);
        CP_COMMIT();
        compute16(smb + (kt&3)*STG, acc, aoff, boff);
    }
}

#define GEMM_PROLOGUE() \
    extern __shared__ char sm[]; \
    const uint32_t smb = smem_u32(sm); \
    const int tid = threadIdx.x; \
    const int w = tid >> 5, wm = w >> 1, wn = w & 1, l = tid & 31; \
    const int fg = l >> 2, ft = l & 3; \
    const int aoff = (wm*64 + (l&15))*PITCH + ((l>>4)<<4); \
    const int boff = (wn*64 + ((l>>4)<<3) + (l&7))*PITCH + (((l>>3)&1)<<4); \
    float acc[4][8][4]; \
    _Pragma("unroll") for (int mi = 0; mi < 4; mi++) \
    _Pragma("unroll") for (int ni = 0; ni < 8; ni++) \
    _Pragma("unroll") for (int j = 0; j < 4; j++) acc[mi][ni][j] = 0.f;

// ======================= pre-round inputs to tf32 bit patterns =======================
__global__ void k_round(const float4* __restrict__ src, float4* __restrict__ dst, int n4)
{
    for (int i = blockIdx.x*blockDim.x + threadIdx.x; i < n4; i += gridDim.x*blockDim.x){
        float4 v = src[i];
        dst[i] = make_float4(rnd(v.x), rnd(v.y), rnd(v.z), rnd(v.w));
    }
}

// ======================= QKV GEMM + fused bias/RoPE + V transpose =======================
__global__ __launch_bounds__(256) void k_qkv(const float* __restrict__ bias,
                                             const float* __restrict__ cs,
                                             const float* __restrict__ sn)
{
    GEMM_PROLOGUE();
    const int n0 = blockIdx.x * TN, m0 = blockIdx.y * TM;
    gemm_cp(smb, acc, g_x + (size_t)m0*DDIM, DDIM, g_w + (size_t)n0*DDIM, DDIM, DDIM/16,
            aoff, boff);

    const int s = n0 >> 11, h = (n0 & 2047) >> 7;
    float* smC = (float*)sm;

    #pragma unroll 1
    for (int pass = 0; pass < 2; pass++){
        __syncthreads();
        if ((wm >> 1) == pass){
            const int wml = wm & 1;
            #pragma unroll
            for (int ni = 0; ni < 8; ni++){
                const int c = wn*64 + ni*8 + 2*ft;
                const float b0 = bias[n0 + c], b1 = bias[n0 + c + 1];
                #pragma unroll
                for (int mi = 0; mi < 4; mi++){
                    const int rr = wml*64 + 16*mi + fg;
                    smC[rr*132 + c]     = acc[mi][ni][0] + b0;
                    smC[rr*132 + c + 1] = acc[mi][ni][1] + b1;
                    smC[(rr+8)*132 + c]     = acc[mi][ni][2] + b0;
                    smC[(rr+8)*132 + c + 1] = acc[mi][ni][3] + b1;
                }
            }
        }
        __syncthreads();

        const int bb = (m0 + pass*128) >> 11;
        const int t0 = (m0 + pass*128) & 2047;
        if (s < 2){
            const int r = tid & 127, half = tid >> 7;
            const int t = t0 + r;
            float* dst = (s ? g_k : g_q) + ((size_t)(bb*NH + h)*TT + t)*HD;
            const float* csr = cs + (size_t)t*HD;
            const float* snr = sn + (size_t)t*HD;
            #pragma unroll
            for (int jj = 0; jj < 8; jj++){
                const int c = half*32 + jj*4;
                float4 x1 = *(const float4*)(smC + r*132 + c);
                float4 x2 = *(const float4*)(smC + r*132 + c + 64);
                float4 c0 = *(const float4*)(csr + c);
                float4 s0 = *(const float4*)(snr + c);
                float4 c1 = *(const float4*)(csr + c + 64);
                float4 s1 = *(const float4*)(snr + c + 64);
                *(float4*)(dst + c) = make_float4(
                    rnd(x1.x*c0.x - x2.x*s0.x), rnd(x1.y*c0.y - x2.y*s0.y),
                    rnd(x1.z*c0.z - x2.z*s0.z), rnd(x1.w*c0.w - x2.w*s0.w));
                *(float4*)(dst + c + 64) = make_float4(
                    rnd(x2.x*c1.x + x1.x*s1.x), rnd(x2.y*c1.y + x1.y*s1.y),
                    rnd(x2.z*c1.z + x1.z*s1.z), rnd(x2.w*c1.w + x1.w*s1.w));
            }
        } else {
            float* dstb = g_vt + (size_t)(bb*NH + h)*HD*TT;
            #pragma unroll
            for (int i = 0; i < 16; i++){
                const int ii = tid + i*256;
                const int d = ii >> 5, tq = ii & 31;
                *(float4*)(dstb + (size_t)d*TT + t0 + tq*4) = make_float4(
                    rnd(smC[(tq*4 + 0)*132 + d]), rnd(smC[(tq*4 + 1)*132 + d]),
                    rnd(smC[(tq*4 + 2)*132 + d]), rnd(smC[(tq*4 + 3)*132 + d]));
            }
        }
    }
}

// ======================= Scores: S = scale * Q K^T, causal tiles only =======================
__global__ __launch_bounds__(256) void k_scores()
{
    const int m0 = blockIdx.y * TM, n0 = blockIdx.x * TN;
    if (n0 > m0 + (TM - 1)) return;
    GEMM_PROLOGUE();
    const int bh = blockIdx.z;
    gemm_cp(smb, acc,
            g_q + (size_t)bh*TT*HD + (size_t)m0*HD, HD,
            g_k + (size_t)bh*TT*HD + (size_t)n0*HD, HD, HD/16, aoff, boff);
    float* C = g_s + (size_t)bh*TT*TT;
    #pragma unroll
    for (int mi = 0; mi < 4; mi++){
        const int rl = m0 + 64*wm + 16*mi + fg;
        #pragma unroll
        for (int ni = 0; ni < 8; ni++){
            const int c = n0 + 64*wn + 8*ni + 2*ft;
            *(float2*)(C + (size_t)rl*TT + c)     = make_float2(acc[mi][ni][0]*SCALE, acc[mi][ni][1]*SCALE);
            *(float2*)(C + (size_t)(rl+8)*TT + c) = make_float2(acc[mi][ni][2]*SCALE, acc[mi][ni][3]*SCALE);
        }
    }
}

// ------------------ PV staging: softmax transform + tf32 round ------------------
static __device__ __forceinline__ void pv_stA(char* buf, int row, int kc, float4 v,
                                              int k0, float mm, float ii, int L)
{
    const int jb = k0 + kc*4;
    uint4 o;
    o.x = (jb + 0 < L) ? f2tf32(__expf(v.x - mm)*ii) : 0u;
    o.y = (jb + 1 < L) ? f2tf32(__expf(v.y - mm)*ii) : 0u;
    o.z = (jb + 2 < L) ? f2tf32(__expf(v.z - mm)*ii) : 0u;
    o.w = (jb + 3 < L) ? f2tf32(__expf(v.w - mm)*ii) : 0u;
    *(uint4*)(buf + row*PITCH + kc*16) = o;
}

// ======================= PV with fused softmax: O = softmax(S) * V =======================
__global__ __launch_bounds__(256) void k_pv()
{
    __shared__ float sM[TM], sInv[TM];
    GEMM_PROLOGUE();
    const int mt = blockIdx.x, bh = blockIdx.y;
    const int m0 = mt * TM;
    const float* Sr = g_s + (size_t)bh*TT*TT + (size_t)m0*TT;
    const float* Vt = g_vt + (size_t)bh*HD*TT;
    const int nIter = (mt + 1) * (TM/16);

    // phase 1: per-row online max/sum over causal length (32 rows per warp)
    #pragma unroll 1
    for (int rr = 0; rr < 32; rr++){
        const int r = w*32 + rr;
        const int L = m0 + r + 1;
        const float* row = Sr + (size_t)r*TT;
        float mloc = -FLT_MAX, sloc = 0.f;
        for (int j0 = l*4; j0 < L; j0 += 128){
            float4 v4 = *(const float4*)(row + j0);
            const float vx[4] = {v4.x, v4.y, v4.z, v4.w};
            float m4 = -FLT_MAX;
            #pragma unroll
            for (int e = 0; e < 4; e++) if (j0 + e < L) m4 = fmaxf(m4, vx[e]);
            if (m4 > mloc){ sloc *= __expf(mloc - m4); mloc = m4; }
            #pragma unroll
            for (int e = 0; e < 4; e++) if (j0 + e < L) sloc += __expf(vx[e] - mloc);
        }
        #pragma unroll
        for (int o = 16; o; o >>= 1){
            const float mo = __shfl_xor_sync(0xffffffffu, mloc, o);
            const float so = __shfl_xor_sync(0xffffffffu, sloc, o);
            const float mn = fmaxf(mloc, mo);
            sloc = sloc*__expf(mloc - mn) + so*__expf(mo - mn);
            mloc = mn;
        }
        if (l == 0){ sM[r] = mloc; sInv[r] = 1.f / sloc; }
    }
    __syncthreads();

    // manual 2-stage mainloop (A: exp transform of 256 rows; B: V^T 128 rows)
    {
        const int rowA = tid;
        const float mr = sM[rowA], ir = sInv[rowA];
        const int L = m0 + rowA + 1;
        const float* Arow = Sr + (size_t)rowA*TT;
        const int rowB = tid >> 1, kb = (tid & 1)*2;
        const float* Brow = Vt + (size_t)rowB*TT + kb*4;

        float4 pa[4], pb[2];
        #pragma unroll
        for (int kc = 0; kc < 4; kc++) pa[kc] = *(const float4*)(Arow + kc*4);
        pb[0] = *(const float4*)(Brow);
        pb[1] = *(const float4*)(Brow + 4);

        #pragma unroll
        for (int kc = 0; kc < 4; kc++) pv_stA(sm, rowA, kc, pa[kc], 0, mr, ir, L);
        *(float4*)(sm + ASZ + rowB*PITCH + kb*16)      = pb[0];
        *(float4*)(sm + ASZ + rowB*PITCH + (kb+1)*16)  = pb[1];
        if (nIter > 1){
            #pragma unroll
            for (int kc = 0; kc < 4; kc++) pa[kc] = *(const float4*)(Arow + 16 + kc*4);
            pb[0] = *(const float4*)(Brow + 16);
            pb[1] = *(const float4*)(Brow + 20);
        }
        __syncthreads();
        for (int kt = 0; kt < nIter; kt++){
            if (kt + 1 < nIter){
                char* nb = sm + ((kt+1)&1)*STG;
                #pragma unroll
                for (int kc = 0; kc < 4; kc++)
                    pv_stA(nb, rowA, kc, pa[kc], (kt+1)*16, mr, ir, L);
                *(float4*)(nb + ASZ + rowB*PITCH + kb*16)     = pb[0];
                *(float4*)(nb + ASZ + rowB*PITCH + (kb+1)*16) = pb[1];
            }
            if (kt + 2 < nIter){
                const int ko = (kt + 2) * 16;
                #pragma unroll
                for (int kc = 0; kc < 4; kc++) pa[kc] = *(const float4*)(Arow + ko + kc*4);
                pb[0] = *(const float4*)(Brow + ko);
                pb[1] = *(const float4*)(Brow + ko + 4);
            }
            compute16(smb + (kt&1)*STG, acc, aoff, boff);
            __syncthreads();
        }
    }

    const int bb = bh >> 4, h = bh & 15;
    #pragma unroll
    for (int mi = 0; mi < 4; mi++){
        const int m = m0 + 64*wm + 16*mi + fg;
        float* d0 = g_attn + ((size_t)(bb*TT + m))*DDIM + h*HD;
        float* d1 = g_attn + ((size_t)(bb*TT + m + 8))*DDIM + h*HD;
        #pragma unroll
        for (int ni = 0; ni < 8; ni++){
            const int c = 64*wn + 8*ni + 2*ft;
            *(float2*)(d0 + c) = make_float2(rnd(acc[mi][ni][0]), rnd(acc[mi][ni][1]));
            *(float2*)(d1 + c) = make_float2(rnd(acc[mi][ni][2]), rnd(acc[mi][ni][3]));
        }
    }
}

// ======================= Output projection =======================
__global__ __launch_bounds__(256) void k_out(const float* __restrict__ bias,
                                             float* __restrict__ Cout)
{
    GEMM_PROLOGUE();
    const int n0 = blockIdx.x * TN, m0 = blockIdx.y * TM;
    gemm_cp(smb, acc, g_attn + (size_t)m0*DDIM, DDIM, g_wo + (size_t)n0*DDIM, DDIM,
            DDIM/16, aoff, boff);
    #pragma unroll
    for (int ni = 0; ni < 8; ni++){
        const int c = n0 + 64*wn + 8*ni + 2*ft;
        const float b0 = bias[c], b1 = bias[c + 1];
        #pragma unroll
        for (int mi = 0; mi < 4; mi++){
            const int m = m0 + 64*wm + 16*mi + fg;
            *(float2*)(Cout + (size_t)m*DDIM + c)     = make_float2(acc[mi][ni][0] + b0, acc[mi][ni][1] + b1);
            *(float2*)(Cout + (size_t)(m+8)*DDIM + c) = make_float2(acc[mi][ni][2] + b0, acc[mi][ni][3] + b1);
        }
    }
}

// ======================= launch =======================
extern "C" void kernel_launch(void* const* d_in, const int* in_sizes, int n_in,
                              void* d_out, int out_size)
{
    (void)in_sizes; (void)n_in; (void)out_size;
    const float* x      = (const float*)d_in[0];
    const float* rc     = (const float*)d_in[1];
    const float* rs     = (const float*)d_in[2];
    const float* qkv_w  = (const float*)d_in[3];
    const float* qkv_b  = (const float*)d_in[4];
    const float* out_w  = (const float*)d_in[5];
    const float* out_b  = (const float*)d_in[6];
    float* out = (float*)d_out;

    cudaFuncSetAttribute(k_qkv,    cudaFuncAttributeMaxDynamicSharedMemorySize, SMEM_ALL);
    cudaFuncSetAttribute(k_scores, cudaFuncAttributeMaxDynamicSharedMemorySize, SMEM_ALL);
    cudaFuncSetAttribute(k_pv,     cudaFuncAttributeMaxDynamicSharedMemorySize, SMEM_ALL);
    cudaFuncSetAttribute(k_out,    cudaFuncAttributeMaxDynamicSharedMemorySize, SMEM_ALL);

    float *px, *pw, *pwo;
    cudaGetSymbolAddress((void**)&px,  g_x);
    cudaGetSymbolAddress((void**)&pw,  g_w);
    cudaGetSymbolAddress((void**)&pwo, g_wo);

    k_round<<<2048, 256>>>((const float4*)x,     (float4*)px,  MROWS*DDIM/4);
    k_round<<<3072, 256>>>((const float4*)qkv_w, (float4*)pw,  E3*DDIM/4);
    k_round<<<1024, 256>>>((const float4*)out_w, (float4*)pwo, DDIM*DDIM/4);

    k_qkv<<<dim3(E3/TN, MROWS/TM), 256, SMEM_ALL>>>(qkv_b, rc, rs);
    k_scores<<<dim3(TT/TN, TT/TM, BH), 256, SMEM_ALL>>>();
    k_pv<<<dim3(TT/TM, BH), 256, SMEM_ALL>>>();
    k_out<<<dim3(DDIM/TN, MROWS/TM), 256, SMEM_ALL>>>(out_b, out);
}

// round 10
// speedup vs baseline: 1.1085x; 1.1085x over previous
#include <cuda_runtime.h>
#include <cstdint>
#include <math.h>
#include <float.h>

#define BD 2
#define TT 2048
#define DDIM 2048
#define NH 16
#define HD 128
#define BH (BD*NH)         // 32
#define MROWS (BD*TT)      // 4096
#define E3 (3*DDIM)        // 6144
#define SCALE 0.08838834764831843f

// CTA tile 128x128, 128 threads (4 warps, 2x2), warp tile 64x64.
// K-chunk 16, row pitch 80B (conflict-free ldmatrix)
#define TM 128
#define TN 128
#define PITCH 80
#define ASZ (TM*PITCH)     // 10240
#define BSZ (TN*PITCH)     // 10240
#define STG (ASZ+BSZ)      // 20480
#define SMEM_ALL (4*STG)   // 81920 (also covers 67584B qkv epilogue staging)

// ------------------ scratch (static device, allocation-free) ------------------
__device__ float g_x [(size_t)MROWS*DDIM];    // tf32-rounded X
__device__ float g_w [(size_t)E3*DDIM];       // tf32-rounded qkv_w
__device__ float g_wo[(size_t)DDIM*DDIM];     // tf32-rounded out_w
__device__ float g_q[(size_t)BH*TT*HD];       // tf32-rounded (RoPE'd)
__device__ float g_k[(size_t)BH*TT*HD];
__device__ float g_vt[(size_t)BH*HD*TT];      // V transposed [bh][d][t], tf32-rounded
__device__ float g_s[(size_t)BH*TT*TT];       // raw scaled scores (fp32)
__device__ float g_attn[(size_t)MROWS*DDIM];  // tf32-rounded

// ------------------ helpers ------------------
static __device__ __forceinline__ uint32_t smem_u32(const void* p){
    uint32_t a;
    asm("{ .reg .u64 t; cvta.to.shared.u64 t, %1; cvt.u32.u64 %0, t; }" : "=r"(a) : "l"(p));
    return a;
}
static __device__ __forceinline__ uint32_t f2tf32(float x){
    uint32_t y; asm("cvt.rn.tf32.f32 %0, %1;" : "=r"(y) : "f"(x)); return y;
}
static __device__ __forceinline__ float rnd(float x){ return __uint_as_float(f2tf32(x)); }

static __device__ __forceinline__ void cp16(uint32_t dst, const void* src){
    uint64_t g;
    asm("cvta.to.global.u64 %0, %1;" : "=l"(g) : "l"(src));
    asm volatile("cp.async.cg.shared.global [%0], [%1], 16;" :: "r"(dst), "l"(g) : "memory");
}
#define CP_COMMIT() asm volatile("cp.async.commit_group;" ::: "memory")
#define CP_WAIT2()  asm volatile("cp.async.wait_group 2;" ::: "memory")

#define LDMX4(r, addr) asm volatile( \
    "ldmatrix.sync.aligned.m8n8.x4.shared.b16 {%0,%1,%2,%3}, [%4];" \
    : "=r"((r)[0]),"=r"((r)[1]),"=r"((r)[2]),"=r"((r)[3]) : "r"(addr))

static __device__ __forceinline__ void mma8(float* c, const uint32_t* a, const uint32_t* b){
    asm volatile(
        "mma.sync.aligned.m16n8k8.row.col.f32.tf32.tf32.f32 "
        "{%0,%1,%2,%3}, {%4,%5,%6,%7}, {%8,%9}, {%0,%1,%2,%3};"
        : "+f"(c[0]), "+f"(c[1]), "+f"(c[2]), "+f"(c[3])
        : "r"(a[0]), "r"(a[1]), "r"(a[2]), "r"(a[3]), "r"(b[0]), "r"(b[1]));
}

// compute one K=16 chunk: warp tile 64x64, 64 MMAs
static __device__ __forceinline__ void compute16(uint32_t stg, float (&acc)[4][8][4],
                                                 int aoff, int boff)
{
    #pragma unroll
    for (int ks = 0; ks < 2; ks++){
        uint32_t a[4][4], b[4][4];
        #pragma unroll
        for (int mi = 0; mi < 4; mi++)
            LDMX4(a[mi], stg + aoff + mi*(16*PITCH) + ks*32);
        #pragma unroll
        for (int p = 0; p < 4; p++)
            LDMX4(b[p], stg + ASZ + boff + p*(16*PITCH) + ks*32);
        #pragma unroll
        for (int mi = 0; mi < 4; mi++)
            #pragma unroll
            for (int p = 0; p < 4; p++){
                mma8(acc[mi][2*p],   a[mi], &b[p][0]);
                mma8(acc[mi][2*p+1], a[mi], &b[p][2]);
            }
    }
}

// cp.async loads for one chunk (A: 128 rows, B: 128 rows; 128 threads)
static __device__ __forceinline__ void cp_issue(uint32_t stg,
    const float* __restrict__ A, size_t lda,
    const float* __restrict__ B, size_t ldb, int k0, int tid)
{
    const int r = tid >> 2, kc = tid & 3;
    #pragma unroll
    for (int j = 0; j < 4; j++)
        cp16(stg + (r + 32*j)*PITCH + kc*16, A + (size_t)(r + 32*j)*lda + k0 + kc*4);
    #pragma unroll
    for (int j = 0; j < 4; j++)
        cp16(stg + ASZ + (r + 32*j)*PITCH + kc*16, B + (size_t)(r + 32*j)*ldb + k0 + kc*4);
}

// C[128,128] += A[128,K]*B[128,K]^T, K = nIter*16, 4-stage cp.async pipeline
static __device__ __forceinline__ void gemm_cp(uint32_t smb, float (&acc)[4][8][4],
    const float* __restrict__ A, size_t lda,
    const float* __restrict__ B, size_t ldb, int nIter, int aoff, int boff)
{
    const int tid = threadIdx.x;
    #pragma unroll
    for (int s = 0; s < 3; s++){
        if (s < nIter) cp_issue(smb + s*STG, A, lda, B, ldb, s*16, tid);
        CP_COMMIT();
    }
    for (int kt = 0; kt < nIter; kt++){
        CP_WAIT2();
        __syncthreads();
        if (kt + 3 < nIter) cp_issue(smb + ((kt+3)&3)*STG, A, lda, B, ldb, (kt+3)*16, tid);
        CP_COMMIT();
        compute16(smb + (kt&3)*STG, acc, aoff, boff);
    }
}

#define GEMM_PROLOGUE() \
    extern __shared__ char sm[]; \
    const uint32_t smb = smem_u32(sm); \
    const int tid = threadIdx.x; \
    const int w = tid >> 5, wm = w >> 1, wn = w & 1, l = tid & 31; \
    const int fg = l >> 2, ft = l & 3; \
    const int aoff = (wm*64 + (l&15))*PITCH + ((l>>4)<<4); \
    const int boff = (wn*64 + ((l>>4)<<3) + (l&7))*PITCH + (((l>>3)&1)<<4); \
    float acc[4][8][4]; \
    _Pragma("unroll") for (int mi = 0; mi < 4; mi++) \
    _Pragma("unroll") for (int ni = 0; ni < 8; ni++) \
    _Pragma("unroll") for (int j = 0; j < 4; j++) acc[mi][ni][j] = 0.f;

// ======================= pre-round inputs to tf32 bit patterns =======================
__global__ void k_round(const float4* __restrict__ src, float4* __restrict__ dst, int n4)
{
    for (int i = blockIdx.x*blockDim.x + threadIdx.x; i < n4; i += gridDim.x*blockDim.x){
        float4 v = src[i];
        dst[i] = make_float4(rnd(v.x), rnd(v.y), rnd(v.z), rnd(v.w));
    }
}

// ======================= QKV GEMM + fused bias/RoPE + V transpose =======================
__global__ __launch_bounds__(128, 2) void k_qkv(const float* __restrict__ bias,
                                                const float* __restrict__ cs,
                                                const float* __restrict__ sn)
{
    GEMM_PROLOGUE();
    const int n0 = blockIdx.x * TN, m0 = blockIdx.y * TM;
    gemm_cp(smb, acc, g_x + (size_t)m0*DDIM, DDIM, g_w + (size_t)n0*DDIM, DDIM, DDIM/16,
            aoff, boff);
    __syncthreads();

    // stage tile (+bias) to smem [128][132]
    float* smC = (float*)sm;
    #pragma unroll
    for (int ni = 0; ni < 8; ni++){
        const int c = wn*64 + ni*8 + 2*ft;
        const float b0 = bias[n0 + c], b1 = bias[n0 + c + 1];
        #pragma unroll
        for (int mi = 0; mi < 4; mi++){
            const int rr = wm*64 + 16*mi + fg;
            smC[rr*132 + c]     = acc[mi][ni][0] + b0;
            smC[rr*132 + c + 1] = acc[mi][ni][1] + b1;
            smC[(rr+8)*132 + c]     = acc[mi][ni][2] + b0;
            smC[(rr+8)*132 + c + 1] = acc[mi][ni][3] + b1;
        }
    }
    __syncthreads();

    const int s = n0 >> 11, h = (n0 & 2047) >> 7;
    const int bb = m0 >> 11, t0 = m0 & 2047;
    if (s < 2){
        // RoPE: each thread owns one row, all 128 columns (pairs c, c+64)
        const int r = tid;
        const int t = t0 + r;
        float* dst = (s ? g_k : g_q) + ((size_t)(bb*NH + h)*TT + t)*HD;
        const float* csr = cs + (size_t)t*HD;
        const float* snr = sn + (size_t)t*HD;
        #pragma unroll
        for (int jj = 0; jj < 16; jj++){
            const int c = jj*4;
            float4 x1 = *(const float4*)(smC + r*132 + c);
            float4 x2 = *(const float4*)(smC + r*132 + c + 64);
            float4 c0 = *(const float4*)(csr + c);
            float4 s0 = *(const float4*)(snr + c);
            float4 c1 = *(const float4*)(csr + c + 64);
            float4 s1 = *(const float4*)(snr + c + 64);
            *(float4*)(dst + c) = make_float4(
                rnd(x1.x*c0.x - x2.x*s0.x), rnd(x1.y*c0.y - x2.y*s0.y),
                rnd(x1.z*c0.z - x2.z*s0.z), rnd(x1.w*c0.w - x2.w*s0.w));
            *(float4*)(dst + c + 64) = make_float4(
                rnd(x2.x*c1.x + x1.x*s1.x), rnd(x2.y*c1.y + x1.y*s1.y),
                rnd(x2.z*c1.z + x1.z*s1.z), rnd(x2.w*c1.w + x1.w*s1.w));
        }
    } else {
        float* dstb = g_vt + (size_t)(bb*NH + h)*HD*TT;
        #pragma unroll
        for (int i = 0; i < 32; i++){
            const int ii = tid + i*128;
            const int d = ii >> 5, tq = ii & 31;
            *(float4*)(dstb + (size_t)d*TT + t0 + tq*4) = make_float4(
                rnd(smC[(tq*4 + 0)*132 + d]), rnd(smC[(tq*4 + 1)*132 + d]),
                rnd(smC[(tq*4 + 2)*132 + d]), rnd(smC[(tq*4 + 3)*132 + d]));
        }
    }
}

// ======================= Scores: S = scale * Q K^T, lower tiles only =======================
__global__ __launch_bounds__(128, 2) void k_scores()
{
    if (blockIdx.x > blockIdx.y) return;
    GEMM_PROLOGUE();
    const int bh = blockIdx.z;
    const int m0 = blockIdx.y * TM, n0 = blockIdx.x * TN;
    gemm_cp(smb, acc,
            g_q + (size_t)bh*TT*HD + (size_t)m0*HD, HD,
            g_k + (size_t)bh*TT*HD + (size_t)n0*HD, HD, HD/16, aoff, boff);
    float* C = g_s + (size_t)bh*TT*TT;
    #pragma unroll
    for (int mi = 0; mi < 4; mi++){
        const int rl = m0 + 64*wm + 16*mi + fg;
        #pragma unroll
        for (int ni = 0; ni < 8; ni++){
            const int c = n0 + 64*wn + 8*ni + 2*ft;
            *(float2*)(C + (size_t)rl*TT + c)     = make_float2(acc[mi][ni][0]*SCALE, acc[mi][ni][1]*SCALE);
            *(float2*)(C + (size_t)(rl+8)*TT + c) = make_float2(acc[mi][ni][2]*SCALE, acc[mi][ni][3]*SCALE);
        }
    }
}

// ------------------ PV staging: softmax transform + tf32 round ------------------
static __device__ __forceinline__ void pv_stA(char* buf, int row, int kc, float4 v,
                                              int k0, float mm, float ii, int L)
{
    const int jb = k0 + kc*4;
    uint4 o;
    o.x = (jb + 0 < L) ? f2tf32(__expf(v.x - mm)*ii) : 0u;
    o.y = (jb + 1 < L) ? f2tf32(__expf(v.y - mm)*ii) : 0u;
    o.z = (jb + 2 < L) ? f2tf32(__expf(v.z - mm)*ii) : 0u;
    o.w = (jb + 3 < L) ? f2tf32(__expf(v.w - mm)*ii) : 0u;
    *(uint4*)(buf + row*PITCH + kc*16) = o;
}

// ======================= PV with fused softmax: O = softmax(S) * V =======================
__global__ __launch_bounds__(128, 2) void k_pv()
{
    __shared__ float sM[TM], sInv[TM];
    GEMM_PROLOGUE();
    const int mt = blockIdx.x, bh = blockIdx.y;
    const int m0 = mt * TM;
    const float* Sr = g_s + (size_t)bh*TT*TT + (size_t)m0*TT;
    const float* Vt = g_vt + (size_t)bh*HD*TT;
    const int nIter = (mt + 1) * (TM/16);

    // phase 1: per-row online max/sum over causal length (32 rows per warp)
    #pragma unroll 1
    for (int rr = 0; rr < 32; rr++){
        const int r = w*32 + rr;
        const int L = m0 + r + 1;
        const float* row = Sr + (size_t)r*TT;
        float mloc = -FLT_MAX, sloc = 0.f;
        for (int j0 = l*4; j0 < L; j0 += 128){
            float4 v4 = *(const float4*)(row + j0);
            const float vx[4] = {v4.x, v4.y, v4.z, v4.w};
            float m4 = -FLT_MAX;
            #pragma unroll
            for (int e = 0; e < 4; e++) if (j0 + e < L) m4 = fmaxf(m4, vx[e]);
            if (m4 > mloc){ sloc *= __expf(mloc - m4); mloc = m4; }
            #pragma unroll
            for (int e = 0; e < 4; e++) if (j0 + e < L) sloc += __expf(vx[e] - mloc);
        }
        #pragma unroll
        for (int o = 16; o; o >>= 1){
            const float mo = __shfl_xor_sync(0xffffffffu, mloc, o);
            const float so = __shfl_xor_sync(0xffffffffu, sloc, o);
            const float mn = fmaxf(mloc, mo);
            sloc = sloc*__expf(mloc - mn) + so*__expf(mo - mn);
            mloc = mn;
        }
        if (l == 0){ sM[r] = mloc; sInv[r] = 1.f / sloc; }
    }
    __syncthreads();

    // manual 2-stage mainloop (A: exp transform; B: V^T; each thread owns one row of each)
    {
        const int row = tid;
        const float mr = sM[row], ir = sInv[row];
        const int L = m0 + row + 1;
        const float* Arow = Sr + (size_t)row*TT;
        const float* Brow = Vt + (size_t)row*TT;

        float4 pa[4], pb[4];
        #pragma unroll
        for (int kc = 0; kc < 4; kc++){
            pa[kc] = *(const float4*)(Arow + kc*4);
            pb[kc] = *(const float4*)(Brow + kc*4);
        }
        #pragma unroll
        for (int kc = 0; kc < 4; kc++){
            pv_stA(sm, row, kc, pa[kc], 0, mr, ir, L);
            *(float4*)(sm + ASZ + row*PITCH + kc*16) = pb[kc];
        }
        if (nIter > 1){
            #pragma unroll
            for (int kc = 0; kc < 4; kc++){
                pa[kc] = *(const float4*)(Arow + 16 + kc*4);
                pb[kc] = *(const float4*)(Brow + 16 + kc*4);
            }
        }
        __syncthreads();
        for (int kt = 0; kt < nIter; kt++){
            if (kt + 1 < nIter){
                char* nb = sm + ((kt+1)&1)*STG;
                #pragma unroll
                for (int kc = 0; kc < 4; kc++){
                    pv_stA(nb, row, kc, pa[kc], (kt+1)*16, mr, ir, L);
                    *(float4*)(nb + ASZ + row*PITCH + kc*16) = pb[kc];
                }
            }
            if (kt + 2 < nIter){
                const int ko = (kt + 2) * 16;
                #pragma unroll
                for (int kc = 0; kc < 4; kc++){
                    pa[kc] = *(const float4*)(Arow + ko + kc*4);
                    pb[kc] = *(const float4*)(Brow + ko + kc*4);
                }
            }
            compute16(smb + (kt&1)*STG, acc, aoff, boff);
            __syncthreads();
        }
    }

    const int bb = bh >> 4, h = bh & 15;
    #pragma unroll
    for (int mi = 0; mi < 4; mi++){
        const int m = m0 + 64*wm + 16*mi + fg;
        float* d0 = g_attn + ((size_t)(bb*TT + m))*DDIM + h*HD;
        float* d1 = g_attn + ((size_t)(bb*TT + m + 8))*DDIM + h*HD;
        #pragma unroll
        for (int ni = 0; ni < 8; ni++){
            const int c = 64*wn + 8*ni + 2*ft;
            *(float2*)(d0 + c) = make_float2(rnd(acc[mi][ni][0]), rnd(acc[mi][ni][1]));
            *(float2*)(d1 + c) = make_float2(rnd(acc[mi][ni][2]), rnd(acc[mi][ni][3]));
        }
    }
}

// ======================= Output projection =======================
__global__ __launch_bounds__(128, 2) void k_out(const float* __restrict__ bias,
                                                float* __restrict__ Cout)
{
    GEMM_PROLOGUE();
    const int n0 = blockIdx.x * TN, m0 = blockIdx.y * TM;
    gemm_cp(smb, acc, g_attn + (size_t)m0*DDIM, DDIM, g_wo + (size_t)n0*DDIM, DDIM,
            DDIM/16, aoff, boff);
    #pragma unroll
    for (int ni = 0; ni < 8; ni++){
        const int c = n0 + 64*wn + 8*ni + 2*ft;
        const float b0 = bias[c], b1 = bias[c + 1];
        #pragma unroll
        for (int mi = 0; mi < 4; mi++){
            const int m = m0 + 64*wm + 16*mi + fg;
            *(float2*)(Cout + (size_t)m*DDIM + c)     = make_float2(acc[mi][ni][0] + b0, acc[mi][ni][1] + b1);
            *(float2*)(Cout + (size_t)(m+8)*DDIM + c) = make_float2(acc[mi][ni][2] + b0, acc[mi][ni][3] + b1);
        }
    }
}

// ======================= launch =======================
extern "C" void kernel_launch(void* const* d_in, const int* in_sizes, int n_in,
                              void* d_out, int out_size)
{
    (void)in_sizes; (void)n_in; (void)out_size;
    const float* x      = (const float*)d_in[0];
    const float* rc     = (const float*)d_in[1];
    const float* rs     = (const float*)d_in[2];
    const float* qkv_w  = (const float*)d_in[3];
    const float* qkv_b  = (const float*)d_in[4];
    const float* out_w  = (const float*)d_in[5];
    const float* out_b  = (const float*)d_in[6];
    float* out = (float*)d_out;

    cudaFuncSetAttribute(k_qkv,    cudaFuncAttributeMaxDynamicSharedMemorySize, SMEM_ALL);
    cudaFuncSetAttribute(k_scores, cudaFuncAttributeMaxDynamicSharedMemorySize, SMEM_ALL);
    cudaFuncSetAttribute(k_pv,     cudaFuncAttributeMaxDynamicSharedMemorySize, SMEM_ALL);
    cudaFuncSetAttribute(k_out,    cudaFuncAttributeMaxDynamicSharedMemorySize, SMEM_ALL);

    float *px, *pw, *pwo;
    cudaGetSymbolAddress((void**)&px,  g_x);
    cudaGetSymbolAddress((void**)&pw,  g_w);
    cudaGetSymbolAddress((void**)&pwo, g_wo);

    k_round<<<2048, 256>>>((const float4*)x,     (float4*)px,  MROWS*DDIM/4);
    k_round<<<3072, 256>>>((const float4*)qkv_w, (float4*)pw,  E3*DDIM/4);
    k_round<<<1024, 256>>>((const float4*)out_w, (float4*)pwo, DDIM*DDIM/4);

    k_qkv<<<dim3(E3/TN, MROWS/TM), 128, SMEM_ALL>>>(qkv_b, rc, rs);
    k_scores<<<dim3(TT/TN, TT/TM, BH), 128, SMEM_ALL>>>();
    k_pv<<<dim3(TT/TM, BH), 128, SMEM_ALL>>>();
    k_out<<<dim3(DDIM/TN, MROWS/TM), 128, SMEM_ALL>>>(out_b, out);
}

// round 11
// speedup vs baseline: 1.3773x; 1.2425x over previous
#include <cuda_runtime.h>
#include <cstdint>
#include <math.h>
#include <float.h>

#define BD 2
#define TT 2048
#define DDIM 2048
#define NH 16
#define HD 128
#define BH (BD*NH)         // 32
#define MROWS (BD*TT)      // 4096
#define E3 (3*DDIM)        // 6144
#define SCALE 0.08838834764831843f

// CTA tile 128x128, 128 threads (4 warps, 2x2), warp tile 64x64.
// K-chunk 16, row pitch 80B (conflict-free ldmatrix)
#define TM 128
#define TN 128
#define PITCH 80
#define ASZ (TM*PITCH)     // 10240
#define BSZ (TN*PITCH)     // 10240
#define STG (ASZ+BSZ)      // 20480
#define SMEM_ALL (4*STG)   // 81920 (also covers 67584B qkv epilogue staging)

// ------------------ scratch (static device, allocation-free) ------------------
__device__ float g_x [(size_t)MROWS*DDIM];    // tf32-rounded X
__device__ float g_w [(size_t)E3*DDIM];       // tf32-rounded qkv_w
__device__ float g_wo[(size_t)DDIM*DDIM];     // tf32-rounded out_w
__device__ float g_q[(size_t)BH*TT*HD];       // tf32-rounded (RoPE'd)
__device__ float g_k[(size_t)BH*TT*HD];
__device__ float g_vt[(size_t)BH*HD*TT];      // V transposed [bh][d][t], tf32-rounded
__device__ float g_s[(size_t)BH*TT*TT];       // raw scaled scores (fp32)
__device__ float g_attn[(size_t)MROWS*DDIM];  // tf32-rounded
// split-softmax partials: per (bh, 64-col group, row)
__device__ float g_pmax[(size_t)BH*32*TT];
__device__ float g_psum[(size_t)BH*32*TT];
__device__ float g_m  [(size_t)BH*TT];
__device__ float g_inv[(size_t)BH*TT];

// ------------------ helpers ------------------
static __device__ __forceinline__ uint32_t smem_u32(const void* p){
    uint32_t a;
    asm("{ .reg .u64 t; cvta.to.shared.u64 t, %1; cvt.u32.u64 %0, t; }" : "=r"(a) : "l"(p));
    return a;
}
static __device__ __forceinline__ uint32_t f2tf32(float x){
    uint32_t y; asm("cvt.rn.tf32.f32 %0, %1;" : "=r"(y) : "f"(x)); return y;
}
static __device__ __forceinline__ float rnd(float x){ return __uint_as_float(f2tf32(x)); }

static __device__ __forceinline__ void cp16(uint32_t dst, const void* src){
    uint64_t g;
    asm("cvta.to.global.u64 %0, %1;" : "=l"(g) : "l"(src));
    asm volatile("cp.async.cg.shared.global [%0], [%1], 16;" :: "r"(dst), "l"(g) : "memory");
}
#define CP_COMMIT() asm volatile("cp.async.commit_group;" ::: "memory")
#define CP_WAIT2()  asm volatile("cp.async.wait_group 2;" ::: "memory")

#define LDMX4(r, addr) asm volatile( \
    "ldmatrix.sync.aligned.m8n8.x4.shared.b16 {%0,%1,%2,%3}, [%4];" \
    : "=r"((r)[0]),"=r"((r)[1]),"=r"((r)[2]),"=r"((r)[3]) : "r"(addr))

static __device__ __forceinline__ void mma8(float* c, const uint32_t* a, const uint32_t* b){
    asm volatile(
        "mma.sync.aligned.m16n8k8.row.col.f32.tf32.tf32.f32 "
        "{%0,%1,%2,%3}, {%4,%5,%6,%7}, {%8,%9}, {%0,%1,%2,%3};"
        : "+f"(c[0]), "+f"(c[1]), "+f"(c[2]), "+f"(c[3])
        : "r"(a[0]), "r"(a[1]), "r"(a[2]), "r"(a[3]), "r"(b[0]), "r"(b[1]));
}

// compute one K=16 chunk: warp tile 64x64, 64 MMAs
static __device__ __forceinline__ void compute16(uint32_t stg, float (&acc)[4][8][4],
                                                 int aoff, int boff)
{
    #pragma unroll
    for (int ks = 0; ks < 2; ks++){
        uint32_t a[4][4], b[4][4];
        #pragma unroll
        for (int mi = 0; mi < 4; mi++)
            LDMX4(a[mi], stg + aoff + mi*(16*PITCH) + ks*32);
        #pragma unroll
        for (int p = 0; p < 4; p++)
            LDMX4(b[p], stg + ASZ + boff + p*(16*PITCH) + ks*32);
        #pragma unroll
        for (int mi = 0; mi < 4; mi++)
            #pragma unroll
            for (int p = 0; p < 4; p++){
                mma8(acc[mi][2*p],   a[mi], &b[p][0]);
                mma8(acc[mi][2*p+1], a[mi], &b[p][2]);
            }
    }
}

// cp.async loads for one chunk (A: 128 rows, B: 128 rows; 128 threads)
static __device__ __forceinline__ void cp_issue(uint32_t stg,
    const float* __restrict__ A, size_t lda,
    const float* __restrict__ B, size_t ldb, int k0, int tid)
{
    const int r = tid >> 2, kc = tid & 3;
    #pragma unroll
    for (int j = 0; j < 4; j++)
        cp16(stg + (r + 32*j)*PITCH + kc*16, A + (size_t)(r + 32*j)*lda + k0 + kc*4);
    #pragma unroll
    for (int j = 0; j < 4; j++)
        cp16(stg + ASZ + (r + 32*j)*PITCH + kc*16, B + (size_t)(r + 32*j)*ldb + k0 + kc*4);
}

// C[128,128] += A[128,K]*B[128,K]^T, K = nIter*16, 4-stage cp.async pipeline
static __device__ __forceinline__ void gemm_cp(uint32_t smb, float (&acc)[4][8][4],
    const float* __restrict__ A, size_t lda,
    const float* __restrict__ B, size_t ldb, int nIter, int aoff, int boff)
{
    const int tid = threadIdx.x;
    #pragma unroll
    for (int s = 0; s < 3; s++){
        if (s < nIter) cp_issue(smb + s*STG, A, lda, B, ldb, s*16, tid);
        CP_COMMIT();
    }
    for (int kt = 0; kt < nIter; kt++){
        CP_WAIT2();
        __syncthreads();
        if (kt + 3 < nIter) cp_issue(smb + ((kt+3)&3)*STG, A, lda, B, ldb, (kt+3)*16, tid);
        CP_COMMIT();
        compute16(smb + (kt&3)*STG, acc, aoff, boff);
    }
}

#define GEMM_PROLOGUE() \
    extern __shared__ char sm[]; \
    const uint32_t smb = smem_u32(sm); \
    const int tid = threadIdx.x; \
    const int w = tid >> 5, wm = w >> 1, wn = w & 1, l = tid & 31; \
    const int fg = l >> 2, ft = l & 3; \
    const int aoff = (wm*64 + (l&15))*PITCH + ((l>>4)<<4); \
    const int boff = (wn*64 + ((l>>4)<<3) + (l&7))*PITCH + (((l>>3)&1)<<4); \
    float acc[4][8][4]; \
    _Pragma("unroll") for (int mi = 0; mi < 4; mi++) \
    _Pragma("unroll") for (int ni = 0; ni < 8; ni++) \
    _Pragma("unroll") for (int j = 0; j < 4; j++) acc[mi][ni][j] = 0.f;

// ======================= pre-round inputs to tf32 bit patterns =======================
__global__ void k_round(const float4* __restrict__ src, float4* __restrict__ dst, int n4)
{
    for (int i = blockIdx.x*blockDim.x + threadIdx.x; i < n4; i += gridDim.x*blockDim.x){
        float4 v = src[i];
        dst[i] = make_float4(rnd(v.x), rnd(v.y), rnd(v.z), rnd(v.w));
    }
}

// ======================= QKV GEMM + fused bias/RoPE + V transpose =======================
__global__ __launch_bounds__(128, 2) void k_qkv(const float* __restrict__ bias,
                                                const float* __restrict__ cs,
                                                const float* __restrict__ sn)
{
    GEMM_PROLOGUE();
    const int n0 = blockIdx.x * TN, m0 = blockIdx.y * TM;
    gemm_cp(smb, acc, g_x + (size_t)m0*DDIM, DDIM, g_w + (size_t)n0*DDIM, DDIM, DDIM/16,
            aoff, boff);
    __syncthreads();

    // stage tile (+bias) to smem [128][132]
    float* smC = (float*)sm;
    #pragma unroll
    for (int ni = 0; ni < 8; ni++){
        const int c = wn*64 + ni*8 + 2*ft;
        const float b0 = bias[n0 + c], b1 = bias[n0 + c + 1];
        #pragma unroll
        for (int mi = 0; mi < 4; mi++){
            const int rr = wm*64 + 16*mi + fg;
            smC[rr*132 + c]     = acc[mi][ni][0] + b0;
            smC[rr*132 + c + 1] = acc[mi][ni][1] + b1;
            smC[(rr+8)*132 + c]     = acc[mi][ni][2] + b0;
            smC[(rr+8)*132 + c + 1] = acc[mi][ni][3] + b1;
        }
    }
    __syncthreads();

    const int s = n0 >> 11, h = (n0 & 2047) >> 7;
    const int bb = m0 >> 11, t0 = m0 & 2047;
    if (s < 2){
        // RoPE: each thread owns one row, all 128 columns (pairs c, c+64)
        const int r = tid;
        const int t = t0 + r;
        float* dst = (s ? g_k : g_q) + ((size_t)(bb*NH + h)*TT + t)*HD;
        const float* csr = cs + (size_t)t*HD;
        const float* snr = sn + (size_t)t*HD;
        #pragma unroll
        for (int jj = 0; jj < 16; jj++){
            const int c = jj*4;
            float4 x1 = *(const float4*)(smC + r*132 + c);
            float4 x2 = *(const float4*)(smC + r*132 + c + 64);
            float4 c0 = *(const float4*)(csr + c);
            float4 s0 = *(const float4*)(snr + c);
            float4 c1 = *(const float4*)(csr + c + 64);
            float4 s1 = *(const float4*)(snr + c + 64);
            *(float4*)(dst + c) = make_float4(
                rnd(x1.x*c0.x - x2.x*s0.x), rnd(x1.y*c0.y - x2.y*s0.y),
                rnd(x1.z*c0.z - x2.z*s0.z), rnd(x1.w*c0.w - x2.w*s0.w));
            *(float4*)(dst + c + 64) = make_float4(
                rnd(x2.x*c1.x + x1.x*s1.x), rnd(x2.y*c1.y + x1.y*s1.y),
                rnd(x2.z*c1.z + x1.z*s1.z), rnd(x2.w*c1.w + x1.w*s1.w));
        }
    } else {
        float* dstb = g_vt + (size_t)(bb*NH + h)*HD*TT;
        #pragma unroll
        for (int i = 0; i < 32; i++){
            const int ii = tid + i*128;
            const int d = ii >> 5, tq = ii & 31;
            *(float4*)(dstb + (size_t)d*TT + t0 + tq*4) = make_float4(
                rnd(smC[(tq*4 + 0)*132 + d]), rnd(smC[(tq*4 + 1)*132 + d]),
                rnd(smC[(tq*4 + 2)*132 + d]), rnd(smC[(tq*4 + 3)*132 + d]));
        }
    }
}

// ======================= Scores + per-tile softmax partials =======================
__global__ __launch_bounds__(128, 2) void k_scores()
{
    if (blockIdx.x > blockIdx.y) return;
    GEMM_PROLOGUE();
    const int bh = blockIdx.z;
    const int m0 = blockIdx.y * TM, n0 = blockIdx.x * TN;
    gemm_cp(smb, acc,
            g_q + (size_t)bh*TT*HD + (size_t)m0*HD, HD,
            g_k + (size_t)bh*TT*HD + (size_t)n0*HD, HD, HD/16, aoff, boff);
    float* C = g_s + (size_t)bh*TT*TT;
    #pragma unroll
    for (int mi = 0; mi < 4; mi++){
        const int rl = m0 + 64*wm + 16*mi + fg;
        #pragma unroll
        for (int ni = 0; ni < 8; ni++){
            const int c = n0 + 64*wn + 8*ni + 2*ft;
            *(float2*)(C + (size_t)rl*TT + c)     = make_float2(acc[mi][ni][0]*SCALE, acc[mi][ni][1]*SCALE);
            *(float2*)(C + (size_t)(rl+8)*TT + c) = make_float2(acc[mi][ni][2]*SCALE, acc[mi][ni][3]*SCALE);
        }
    }
    // per-row partial (max, sumexp) over this warp's 64-column group, causal-masked
    const int g64 = (n0 >> 6) + wn;
    float* pm = g_pmax + ((size_t)bh*32 + g64)*TT;
    float* ps = g_psum + ((size_t)bh*32 + g64)*TT;
    #pragma unroll
    for (int mi = 0; mi < 4; mi++){
        #pragma unroll
        for (int hi = 0; hi < 2; hi++){
            const int rl = m0 + 64*wm + 16*mi + fg + 8*hi;
            float vv[16];
            float rmax = -FLT_MAX;
            #pragma unroll
            for (int ni = 0; ni < 8; ni++){
                #pragma unroll
                for (int e = 0; e < 2; e++){
                    const int c = n0 + 64*wn + 8*ni + 2*ft + e;
                    const float v = acc[mi][ni][hi*2 + e]*SCALE;
                    const bool ok = (c <= rl);
                    vv[ni*2 + e] = ok ? v : -FLT_MAX;
                    if (ok) rmax = fmaxf(rmax, v);
                }
            }
            rmax = fmaxf(rmax, __shfl_xor_sync(0xffffffffu, rmax, 1));
            rmax = fmaxf(rmax, __shfl_xor_sync(0xffffffffu, rmax, 2));
            float s = 0.f;
            #pragma unroll
            for (int e = 0; e < 16; e++)
                if (vv[e] > -FLT_MAX) s += __expf(vv[e] - rmax);
            s += __shfl_xor_sync(0xffffffffu, s, 1);
            s += __shfl_xor_sync(0xffffffffu, s, 2);
            if (ft == 0){ pm[rl] = rmax; ps[rl] = s; }
        }
    }
}

// ======================= finalize softmax stats: reduce partials per row =======================
__global__ void k_finalize()
{
    const int idx = blockIdx.x*blockDim.x + threadIdx.x;   // 0..BH*TT-1
    if (idx >= BH*TT) return;
    const int bh = idx >> 11, row = idx & 2047;
    const int gmax = ((row >> 7) << 1) + 1;
    const float* pm = g_pmax + (size_t)bh*32*TT;
    const float* ps = g_psum + (size_t)bh*32*TT;
    float m = -FLT_MAX;
    for (int g = 0; g <= gmax; g++) m = fmaxf(m, pm[(size_t)g*TT + row]);
    float s = 0.f;
    for (int g = 0; g <= gmax; g++){
        const float pmg = pm[(size_t)g*TT + row];
        if (pmg > -FLT_MAX) s += ps[(size_t)g*TT + row] * __expf(pmg - m);
    }
    g_m[idx] = m;
    g_inv[idx] = 1.f / s;
}

// ------------------ PV staging: softmax transform + tf32 round ------------------
static __device__ __forceinline__ void pv_stA(char* buf, int row, int kc, float4 v,
                                              int k0, float mm, float ii, int L)
{
    const int jb = k0 + kc*4;
    uint4 o;
    o.x = (jb + 0 < L) ? f2tf32(__expf(v.x - mm)*ii) : 0u;
    o.y = (jb + 1 < L) ? f2tf32(__expf(v.y - mm)*ii) : 0u;
    o.z = (jb + 2 < L) ? f2tf32(__expf(v.z - mm)*ii) : 0u;
    o.w = (jb + 3 < L) ? f2tf32(__expf(v.w - mm)*ii) : 0u;
    *(uint4*)(buf + row*PITCH + kc*16) = o;
}

// ======================= PV with fused softmax: O = softmax(S) * V =======================
__global__ __launch_bounds__(128, 2) void k_pv()
{
    __shared__ float sM[TM], sInv[TM];
    GEMM_PROLOGUE();
    const int mt = blockIdx.x, bh = blockIdx.y;
    const int m0 = mt * TM;
    const float* Sr = g_s + (size_t)bh*TT*TT + (size_t)m0*TT;
    const float* Vt = g_vt + (size_t)bh*HD*TT;
    const int nIter = (mt + 1) * (TM/16);

    // load precomputed per-row stats
    sM[tid]   = g_m  [(size_t)bh*TT + m0 + tid];
    sInv[tid] = g_inv[(size_t)bh*TT + m0 + tid];
    __syncthreads();

    // manual 2-stage mainloop (A: exp transform; B: V^T; each thread owns one row of each)
    {
        const int row = tid;
        const float mr = sM[row], ir = sInv[row];
        const int L = m0 + row + 1;
        const float* Arow = Sr + (size_t)row*TT;
        const float* Brow = Vt + (size_t)row*TT;

        float4 pa[4], pb[4];
        #pragma unroll
        for (int kc = 0; kc < 4; kc++){
            pa[kc] = *(const float4*)(Arow + kc*4);
            pb[kc] = *(const float4*)(Brow + kc*4);
        }
        #pragma unroll
        for (int kc = 0; kc < 4; kc++){
            pv_stA(sm, row, kc, pa[kc], 0, mr, ir, L);
            *(float4*)(sm + ASZ + row*PITCH + kc*16) = pb[kc];
        }
        if (nIter > 1){
            #pragma unroll
            for (int kc = 0; kc < 4; kc++){
                pa[kc] = *(const float4*)(Arow + 16 + kc*4);
                pb[kc] = *(const float4*)(Brow + 16 + kc*4);
            }
        }
        __syncthreads();
        for (int kt = 0; kt < nIter; kt++){
            if (kt + 1 < nIter){
                char* nb = sm + ((kt+1)&1)*STG;
                #pragma unroll
                for (int kc = 0; kc < 4; kc++){
                    pv_stA(nb, row, kc, pa[kc], (kt+1)*16, mr, ir, L);
                    *(float4*)(nb + ASZ + row*PITCH + kc*16) = pb[kc];
                }
            }
            if (kt + 2 < nIter){
                const int ko = (kt + 2) * 16;
                #pragma unroll
                for (int kc = 0; kc < 4; kc++){
                    pa[kc] = *(const float4*)(Arow + ko + kc*4);
                    pb[kc] = *(const float4*)(Brow + ko + kc*4);
                }
            }
            compute16(smb + (kt&1)*STG, acc, aoff, boff);
            __syncthreads();
        }
    }

    const int bb = bh >> 4, h = bh & 15;
    #pragma unroll
    for (int mi = 0; mi < 4; mi++){
        const int m = m0 + 64*wm + 16*mi + fg;
        float* d0 = g_attn + ((size_t)(bb*TT + m))*DDIM + h*HD;
        float* d1 = g_attn + ((size_t)(bb*TT + m + 8))*DDIM + h*HD;
        #pragma unroll
        for (int ni = 0; ni < 8; ni++){
            const int c = 64*wn + 8*ni + 2*ft;
            *(float2*)(d0 + c) = make_float2(rnd(acc[mi][ni][0]), rnd(acc[mi][ni][1]));
            *(float2*)(d1 + c) = make_float2(rnd(acc[mi][ni][2]), rnd(acc[mi][ni][3]));
        }
    }
}

// ======================= Output projection =======================
__global__ __launch_bounds__(128, 2) void k_out(const float* __restrict__ bias,
                                                float* __restrict__ Cout)
{
    GEMM_PROLOGUE();
    const int n0 = blockIdx.x * TN, m0 = blockIdx.y * TM;
    gemm_cp(smb, acc, g_attn + (size_t)m0*DDIM, DDIM, g_wo + (size_t)n0*DDIM, DDIM,
            DDIM/16, aoff, boff);
    #pragma unroll
    for (int ni = 0; ni < 8; ni++){
        const int c = n0 + 64*wn + 8*ni + 2*ft;
        const float b0 = bias[c], b1 = bias[c + 1];
        #pragma unroll
        for (int mi = 0; mi < 4; mi++){
            const int m = m0 + 64*wm + 16*mi + fg;
            *(float2*)(Cout + (size_t)m*DDIM + c)     = make_float2(acc[mi][ni][0] + b0, acc[mi][ni][1] + b1);
            *(float2*)(Cout + (size_t)(m+8)*DDIM + c) = make_float2(acc[mi][ni][2] + b0, acc[mi][ni][3] + b1);
        }
    }
}

// ======================= launch =======================
extern "C" void kernel_launch(void* const* d_in, const int* in_sizes, int n_in,
                              void* d_out, int out_size)
{
    (void)in_sizes; (void)n_in; (void)out_size;
    const float* x      = (const float*)d_in[0];
    const float* rc     = (const float*)d_in[1];
    const float* rs     = (const float*)d_in[2];
    const float* qkv_w  = (const float*)d_in[3];
    const float* qkv_b  = (const float*)d_in[4];
    const float* out_w  = (const float*)d_in[5];
    const float* out_b  = (const float*)d_in[6];
    float* out = (float*)d_out;

    cudaFuncSetAttribute(k_qkv,    cudaFuncAttributeMaxDynamicSharedMemorySize, SMEM_ALL);
    cudaFuncSetAttribute(k_scores, cudaFuncAttributeMaxDynamicSharedMemorySize, SMEM_ALL);
    cudaFuncSetAttribute(k_pv,     cudaFuncAttributeMaxDynamicSharedMemorySize, SMEM_ALL);
    cudaFuncSetAttribute(k_out,    cudaFuncAttributeMaxDynamicSharedMemorySize, SMEM_ALL);

    float *px, *pw, *pwo;
    cudaGetSymbolAddress((void**)&px,  g_x);
    cudaGetSymbolAddress((void**)&pw,  g_w);
    cudaGetSymbolAddress((void**)&pwo, g_wo);

    k_round<<<2048, 256>>>((const float4*)x,     (float4*)px,  MROWS*DDIM/4);
    k_round<<<3072, 256>>>((const float4*)qkv_w, (float4*)pw,  E3*DDIM/4);
    k_round<<<1024, 256>>>((const float4*)out_w, (float4*)pwo, DDIM*DDIM/4);

    k_qkv<<<dim3(E3/TN, MROWS/TM), 128, SMEM_ALL>>>(qkv_b, rc, rs);
    k_scores<<<dim3(TT/TN, TT/TM, BH), 128, SMEM_ALL>>>();
    k_finalize<<<(BH*TT + 255)/256, 256>>>();
    k_pv<<<dim3(TT/TM, BH), 128, SMEM_ALL>>>();
    k_out<<<dim3(DDIM/TN, MROWS/TM), 128, SMEM_ALL>>>(out_b, out);
}

// round 12
// speedup vs baseline: 1.4245x; 1.0342x over previous
#include <cuda_runtime.h>
#include <cstdint>
#include <math.h>
#include <float.h>

#define BD 2
#define TT 2048
#define DDIM 2048
#define NH 16
#define HD 128
#define BH (BD*NH)         // 32
#define MROWS (BD*TT)      // 4096
#define E3 (3*DDIM)        // 6144
#define SCALE 0.08838834764831843f

// GEMM path: CTA tile 128x128, 128 threads (4 warps 2x2), warp tile 64x64.
// K-chunk 32, pitch 144B (conflict-free ldmatrix), 3-stage cp.async pipeline.
#define P32 144
#define ASZ32 (128*P32)        // 18432
#define STG32 (2*ASZ32)        // 36864
#define SMEM_ALL (3*STG32)     // 110592 (covers 67584B qkv epilogue staging)

// PV path keeps K-chunk 16 (pitch 80), 2 manual stages (40960B < SMEM_ALL)
#define P16 80
#define ASZ16 (128*P16)        // 10240
#define STG16 (2*ASZ16)        // 20480

// ------------------ scratch (static device, allocation-free) ------------------
__device__ float g_x [(size_t)MROWS*DDIM];    // tf32-rounded X
__device__ float g_w [(size_t)E3*DDIM];       // tf32-rounded qkv_w
__device__ float g_wo[(size_t)DDIM*DDIM];     // tf32-rounded out_w
__device__ float g_q[(size_t)BH*TT*HD];       // tf32-rounded (RoPE'd)
__device__ float g_k[(size_t)BH*TT*HD];
__device__ float g_vt[(size_t)BH*HD*TT];      // V transposed [bh][d][t], tf32-rounded
__device__ float g_s[(size_t)BH*TT*TT];       // raw scaled scores (fp32)
__device__ float g_attn[(size_t)MROWS*DDIM];  // tf32-rounded
// split-softmax partials: per (bh, 64-col group, row)
__device__ float g_pmax[(size_t)BH*32*TT];
__device__ float g_psum[(size_t)BH*32*TT];
__device__ float g_m  [(size_t)BH*TT];
__device__ float g_inv[(size_t)BH*TT];

// ------------------ helpers ------------------
static __device__ __forceinline__ uint32_t smem_u32(const void* p){
    uint32_t a;
    asm("{ .reg .u64 t; cvta.to.shared.u64 t, %1; cvt.u32.u64 %0, t; }" : "=r"(a) : "l"(p));
    return a;
}
static __device__ __forceinline__ uint32_t f2tf32(float x){
    uint32_t y; asm("cvt.rn.tf32.f32 %0, %1;" : "=r"(y) : "f"(x)); return y;
}
static __device__ __forceinline__ float rnd(float x){ return __uint_as_float(f2tf32(x)); }

static __device__ __forceinline__ void cp16(uint32_t dst, const void* src){
    uint64_t g;
    asm("cvta.to.global.u64 %0, %1;" : "=l"(g) : "l"(src));
    asm volatile("cp.async.cg.shared.global [%0], [%1], 16;" :: "r"(dst), "l"(g) : "memory");
}
#define CP_COMMIT() asm volatile("cp.async.commit_group;" ::: "memory")
#define CP_WAIT1()  asm volatile("cp.async.wait_group 1;" ::: "memory")

#define LDMX4(r, addr) asm volatile( \
    "ldmatrix.sync.aligned.m8n8.x4.shared.b16 {%0,%1,%2,%3}, [%4];" \
    : "=r"((r)[0]),"=r"((r)[1]),"=r"((r)[2]),"=r"((r)[3]) : "r"(addr))

static __device__ __forceinline__ void mma8(float* c, const uint32_t* a, const uint32_t* b){
    asm volatile(
        "mma.sync.aligned.m16n8k8.row.col.f32.tf32.tf32.f32 "
        "{%0,%1,%2,%3}, {%4,%5,%6,%7}, {%8,%9}, {%0,%1,%2,%3};"
        : "+f"(c[0]), "+f"(c[1]), "+f"(c[2]), "+f"(c[3])
        : "r"(a[0]), "r"(a[1]), "r"(a[2]), "r"(a[3]), "r"(b[0]), "r"(b[1]));
}

// compute one K-chunk (NKS ks-slices of K=8): warp tile 64x64, 16*NKS MMAs
template<int NKS, int P, int ASZ>
static __device__ __forceinline__ void compute_chunk(uint32_t stg, float (&acc)[4][8][4],
                                                     int aoff, int boff)
{
    #pragma unroll
    for (int ks = 0; ks < NKS; ks++){
        uint32_t a[4][4], b[4][4];
        #pragma unroll
        for (int mi = 0; mi < 4; mi++)
            LDMX4(a[mi], stg + aoff + mi*(16*P) + ks*32);
        #pragma unroll
        for (int p = 0; p < 4; p++)
            LDMX4(b[p], stg + ASZ + boff + p*(16*P) + ks*32);
        #pragma unroll
        for (int mi = 0; mi < 4; mi++)
            #pragma unroll
            for (int p = 0; p < 4; p++){
                mma8(acc[mi][2*p],   a[mi], &b[p][0]);
                mma8(acc[mi][2*p+1], a[mi], &b[p][2]);
            }
    }
}

// cp.async loads for one K=32 chunk (A,B: 128 rows x 128B; 128 threads)
static __device__ __forceinline__ void cp_issue32(uint32_t stg,
    const float* __restrict__ A, size_t lda,
    const float* __restrict__ B, size_t ldb, int k0, int tid)
{
    const int kc = tid & 7, r0 = tid >> 3;   // 8 x 16B segments, 16 row-groups
    #pragma unroll
    for (int j = 0; j < 8; j++){
        const int r = r0 + 16*j;
        cp16(stg + r*P32 + kc*16, A + (size_t)r*lda + k0 + kc*4);
    }
    #pragma unroll
    for (int j = 0; j < 8; j++){
        const int r = r0 + 16*j;
        cp16(stg + ASZ32 + r*P32 + kc*16, B + (size_t)r*ldb + k0 + kc*4);
    }
}

// C[128,128] += A[128,K]*B[128,K]^T, K = nIter*32, 3-stage cp.async pipeline
static __device__ __forceinline__ void gemm_cp(uint32_t smb, float (&acc)[4][8][4],
    const float* __restrict__ A, size_t lda,
    const float* __restrict__ B, size_t ldb, int nIter, int aoff, int boff)
{
    const int tid = threadIdx.x;
    #pragma unroll
    for (int s = 0; s < 2; s++){
        if (s < nIter) cp_issue32(smb + s*STG32, A, lda, B, ldb, s*32, tid);
        CP_COMMIT();
    }
    int stq = 2;                    // next stage slot to fill
    for (int kt = 0; kt < nIter; kt++){
        CP_WAIT1();
        __syncthreads();
        if (kt + 2 < nIter){
            cp_issue32(smb + stq*STG32, A, lda, B, ldb, (kt+2)*32, tid);
            if (++stq == 3) stq = 0;
        }
        CP_COMMIT();
        int cur = kt % 3;
        compute_chunk<4, P32, ASZ32>(smb + cur*STG32, acc, aoff, boff);
    }
}

#define GEMM_PROLOGUE(P) \
    extern __shared__ char sm[]; \
    const uint32_t smb = smem_u32(sm); \
    const int tid = threadIdx.x; \
    const int w = tid >> 5, wm = w >> 1, wn = w & 1, l = tid & 31; \
    const int fg = l >> 2, ft = l & 3; \
    const int aoff = (wm*64 + (l&15))*(P) + ((l>>4)<<4); \
    const int boff = (wn*64 + ((l>>4)<<3) + (l&7))*(P) + (((l>>3)&1)<<4); \
    float acc[4][8][4]; \
    _Pragma("unroll") for (int mi = 0; mi < 4; mi++) \
    _Pragma("unroll") for (int ni = 0; ni < 8; ni++) \
    _Pragma("unroll") for (int j = 0; j < 4; j++) acc[mi][ni][j] = 0.f;

// ======================= pre-round inputs to tf32 bit patterns =======================
__global__ void k_round(const float4* __restrict__ src, float4* __restrict__ dst, int n4)
{
    for (int i = blockIdx.x*blockDim.x + threadIdx.x; i < n4; i += gridDim.x*blockDim.x){
        float4 v = src[i];
        dst[i] = make_float4(rnd(v.x), rnd(v.y), rnd(v.z), rnd(v.w));
    }
}

// ======================= QKV GEMM + fused bias/RoPE + V transpose =======================
__global__ __launch_bounds__(128, 2) void k_qkv(const float* __restrict__ bias,
                                                const float* __restrict__ cs,
                                                const float* __restrict__ sn)
{
    GEMM_PROLOGUE(P32);
    const int n0 = blockIdx.x * 128, m0 = blockIdx.y * 128;
    gemm_cp(smb, acc, g_x + (size_t)m0*DDIM, DDIM, g_w + (size_t)n0*DDIM, DDIM, DDIM/32,
            aoff, boff);
    __syncthreads();

    // stage tile (+bias) to smem [128][132]
    float* smC = (float*)sm;
    #pragma unroll
    for (int ni = 0; ni < 8; ni++){
        const int c = wn*64 + ni*8 + 2*ft;
        const float b0 = bias[n0 + c], b1 = bias[n0 + c + 1];
        #pragma unroll
        for (int mi = 0; mi < 4; mi++){
            const int rr = wm*64 + 16*mi + fg;
            smC[rr*132 + c]     = acc[mi][ni][0] + b0;
            smC[rr*132 + c + 1] = acc[mi][ni][1] + b1;
            smC[(rr+8)*132 + c]     = acc[mi][ni][2] + b0;
            smC[(rr+8)*132 + c + 1] = acc[mi][ni][3] + b1;
        }
    }
    __syncthreads();

    const int s = n0 >> 11, h = (n0 & 2047) >> 7;
    const int bb = m0 >> 11, t0 = m0 & 2047;
    if (s < 2){
        // RoPE: each thread owns one row, all 128 columns (pairs c, c+64)
        const int r = tid;
        const int t = t0 + r;
        float* dst = (s ? g_k : g_q) + ((size_t)(bb*NH + h)*TT + t)*HD;
        const float* csr = cs + (size_t)t*HD;
        const float* snr = sn + (size_t)t*HD;
        #pragma unroll
        for (int jj = 0; jj < 16; jj++){
            const int c = jj*4;
            float4 x1 = *(const float4*)(smC + r*132 + c);
            float4 x2 = *(const float4*)(smC + r*132 + c + 64);
            float4 c0 = *(const float4*)(csr + c);
            float4 s0 = *(const float4*)(snr + c);
            float4 c1 = *(const float4*)(csr + c + 64);
            float4 s1 = *(const float4*)(snr + c + 64);
            *(float4*)(dst + c) = make_float4(
                rnd(x1.x*c0.x - x2.x*s0.x), rnd(x1.y*c0.y - x2.y*s0.y),
                rnd(x1.z*c0.z - x2.z*s0.z), rnd(x1.w*c0.w - x2.w*s0.w));
            *(float4*)(dst + c + 64) = make_float4(
                rnd(x2.x*c1.x + x1.x*s1.x), rnd(x2.y*c1.y + x1.y*s1.y),
                rnd(x2.z*c1.z + x1.z*s1.z), rnd(x2.w*c1.w + x1.w*s1.w));
        }
    } else {
        float* dstb = g_vt + (size_t)(bb*NH + h)*HD*TT;
        #pragma unroll
        for (int i = 0; i < 32; i++){
            const int ii = tid + i*128;
            const int d = ii >> 5, tq = ii & 31;
            *(float4*)(dstb + (size_t)d*TT + t0 + tq*4) = make_float4(
                rnd(smC[(tq*4 + 0)*132 + d]), rnd(smC[(tq*4 + 1)*132 + d]),
                rnd(smC[(tq*4 + 2)*132 + d]), rnd(smC[(tq*4 + 3)*132 + d]));
        }
    }
}

// ======================= Scores + per-tile softmax partials =======================
__global__ __launch_bounds__(128, 2) void k_scores()
{
    if (blockIdx.x > blockIdx.y) return;
    GEMM_PROLOGUE(P32);
    const int bh = blockIdx.z;
    const int m0 = blockIdx.y * 128, n0 = blockIdx.x * 128;
    gemm_cp(smb, acc,
            g_q + (size_t)bh*TT*HD + (size_t)m0*HD, HD,
            g_k + (size_t)bh*TT*HD + (size_t)n0*HD, HD, HD/32, aoff, boff);
    float* C = g_s + (size_t)bh*TT*TT;
    #pragma unroll
    for (int mi = 0; mi < 4; mi++){
        const int rl = m0 + 64*wm + 16*mi + fg;
        #pragma unroll
        for (int ni = 0; ni < 8; ni++){
            const int c = n0 + 64*wn + 8*ni + 2*ft;
            *(float2*)(C + (size_t)rl*TT + c)     = make_float2(acc[mi][ni][0]*SCALE, acc[mi][ni][1]*SCALE);
            *(float2*)(C + (size_t)(rl+8)*TT + c) = make_float2(acc[mi][ni][2]*SCALE, acc[mi][ni][3]*SCALE);
        }
    }
    // per-row partial (max, sumexp) over this warp's 64-column group, causal-masked
    const int g64 = (n0 >> 6) + wn;
    float* pm = g_pmax + ((size_t)bh*32 + g64)*TT;
    float* ps = g_psum + ((size_t)bh*32 + g64)*TT;
    #pragma unroll
    for (int mi = 0; mi < 4; mi++){
        #pragma unroll
        for (int hi = 0; hi < 2; hi++){
            const int rl = m0 + 64*wm + 16*mi + fg + 8*hi;
            float vv[16];
            float rmax = -FLT_MAX;
            #pragma unroll
            for (int ni = 0; ni < 8; ni++){
                #pragma unroll
                for (int e = 0; e < 2; e++){
                    const int c = n0 + 64*wn + 8*ni + 2*ft + e;
                    const float v = acc[mi][ni][hi*2 + e]*SCALE;
                    const bool ok = (c <= rl);
                    vv[ni*2 + e] = ok ? v : -FLT_MAX;
                    if (ok) rmax = fmaxf(rmax, v);
                }
            }
            rmax = fmaxf(rmax, __shfl_xor_sync(0xffffffffu, rmax, 1));
            rmax = fmaxf(rmax, __shfl_xor_sync(0xffffffffu, rmax, 2));
            float s = 0.f;
            #pragma unroll
            for (int e = 0; e < 16; e++)
                if (vv[e] > -FLT_MAX) s += __expf(vv[e] - rmax);
            s += __shfl_xor_sync(0xffffffffu, s, 1);
            s += __shfl_xor_sync(0xffffffffu, s, 2);
            if (ft == 0){ pm[rl] = rmax; ps[rl] = s; }
        }
    }
}

// ======================= finalize softmax stats: reduce partials per row =======================
__global__ void k_finalize()
{
    const int idx = blockIdx.x*blockDim.x + threadIdx.x;   // 0..BH*TT-1
    if (idx >= BH*TT) return;
    const int bh = idx >> 11, row = idx & 2047;
    const int gmax = ((row >> 7) << 1) + 1;
    const float* pm = g_pmax + (size_t)bh*32*TT;
    const float* ps = g_psum + (size_t)bh*32*TT;
    float m = -FLT_MAX;
    for (int g = 0; g <= gmax; g++) m = fmaxf(m, pm[(size_t)g*TT + row]);
    float s = 0.f;
    for (int g = 0; g <= gmax; g++){
        const float pmg = pm[(size_t)g*TT + row];
        if (pmg > -FLT_MAX) s += ps[(size_t)g*TT + row] * __expf(pmg - m);
    }
    g_m[idx] = m;
    g_inv[idx] = 1.f / s;
}

// ------------------ PV staging: softmax transform + tf32 round ------------------
static __device__ __forceinline__ void pv_stA(char* buf, int row, int kc, float4 v,
                                              int k0, float mm, float ii, int L)
{
    const int jb = k0 + kc*4;
    uint4 o;
    o.x = (jb + 0 < L) ? f2tf32(__expf(v.x - mm)*ii) : 0u;
    o.y = (jb + 1 < L) ? f2tf32(__expf(v.y - mm)*ii) : 0u;
    o.z = (jb + 2 < L) ? f2tf32(__expf(v.z - mm)*ii) : 0u;
    o.w = (jb + 3 < L) ? f2tf32(__expf(v.w - mm)*ii) : 0u;
    *(uint4*)(buf + row*P16 + kc*16) = o;
}

// ======================= PV with fused softmax: O = softmax(S) * V =======================
__global__ __launch_bounds__(128, 2) void k_pv()
{
    __shared__ float sM[128], sInv[128];
    GEMM_PROLOGUE(P16);
    const int mt = blockIdx.x, bh = blockIdx.y;
    const int m0 = mt * 128;
    const float* Sr = g_s + (size_t)bh*TT*TT + (size_t)m0*TT;
    const float* Vt = g_vt + (size_t)bh*HD*TT;
    const int nIter = (mt + 1) * 8;

    // load precomputed per-row stats
    sM[tid]   = g_m  [(size_t)bh*TT + m0 + tid];
    sInv[tid] = g_inv[(size_t)bh*TT + m0 + tid];
    __syncthreads();

    // manual 2-stage K16 mainloop (A: exp transform; B: V^T; one row per thread)
    {
        const int row = tid;
        const float mr = sM[row], ir = sInv[row];
        const int L = m0 + row + 1;
        const float* Arow = Sr + (size_t)row*TT;
        const float* Brow = Vt + (size_t)row*TT;

        float4 pa[4], pb[4];
        #pragma unroll
        for (int kc = 0; kc < 4; kc++){
            pa[kc] = *(const float4*)(Arow + kc*4);
            pb[kc] = *(const float4*)(Brow + kc*4);
        }
        #pragma unroll
        for (int kc = 0; kc < 4; kc++){
            pv_stA(sm, row, kc, pa[kc], 0, mr, ir, L);
            *(float4*)(sm + ASZ16 + row*P16 + kc*16) = pb[kc];
        }
        if (nIter > 1){
            #pragma unroll
            for (int kc = 0; kc < 4; kc++){
                pa[kc] = *(const float4*)(Arow + 16 + kc*4);
                pb[kc] = *(const float4*)(Brow + 16 + kc*4);
            }
        }
        __syncthreads();
        for (int kt = 0; kt < nIter; kt++){
            if (kt + 1 < nIter){
                char* nb = sm + ((kt+1)&1)*STG16;
                #pragma unroll
                for (int kc = 0; kc < 4; kc++){
                    pv_stA(nb, row, kc, pa[kc], (kt+1)*16, mr, ir, L);
                    *(float4*)(nb + ASZ16 + row*P16 + kc*16) = pb[kc];
                }
            }
            if (kt + 2 < nIter){
                const int ko = (kt + 2) * 16;
                #pragma unroll
                for (int kc = 0; kc < 4; kc++){
                    pa[kc] = *(const float4*)(Arow + ko + kc*4);
                    pb[kc] = *(const float4*)(Brow + ko + kc*4);
                }
            }
            compute_chunk<2, P16, ASZ16>(smb + (kt&1)*STG16, acc, aoff, boff);
            __syncthreads();
        }
    }

    const int bb = bh >> 4, h = bh & 15;
    #pragma unroll
    for (int mi = 0; mi < 4; mi++){
        const int m = m0 + 64*wm + 16*mi + fg;
        float* d0 = g_attn + ((size_t)(bb*TT + m))*DDIM + h*HD;
        float* d1 = g_attn + ((size_t)(bb*TT + m + 8))*DDIM + h*HD;
        #pragma unroll
        for (int ni = 0; ni < 8; ni++){
            const int c = 64*wn + 8*ni + 2*ft;
            *(float2*)(d0 + c) = make_float2(rnd(acc[mi][ni][0]), rnd(acc[mi][ni][1]));
            *(float2*)(d1 + c) = make_float2(rnd(acc[mi][ni][2]), rnd(acc[mi][ni][3]));
        }
    }
}

// ======================= Output projection =======================
__global__ __launch_bounds__(128, 2) void k_out(const float* __restrict__ bias,
                                                float* __restrict__ Cout)
{
    GEMM_PROLOGUE(P32);
    const int n0 = blockIdx.x * 128, m0 = blockIdx.y * 128;
    gemm_cp(smb, acc, g_attn + (size_t)m0*DDIM, DDIM, g_wo + (size_t)n0*DDIM, DDIM,
            DDIM/32, aoff, boff);
    #pragma unroll
    for (int ni = 0; ni < 8; ni++){
        const int c = n0 + 64*wn + 8*ni + 2*ft;
        const float b0 = bias[c], b1 = bias[c + 1];
        #pragma unroll
        for (int mi = 0; mi < 4; mi++){
            const int m = m0 + 64*wm + 16*mi + fg;
            *(float2*)(Cout + (size_t)m*DDIM + c)     = make_float2(acc[mi][ni][0] + b0, acc[mi][ni][1] + b1);
            *(float2*)(Cout + (size_t)(m+8)*DDIM + c) = make_float2(acc[mi][ni][2] + b0, acc[mi][ni][3] + b1);
        }
    }
}

// ======================= launch =======================
extern "C" void kernel_launch(void* const* d_in, const int* in_sizes, int n_in,
                              void* d_out, int out_size)
{
    (void)in_sizes; (void)n_in; (void)out_size;
    const float* x      = (const float*)d_in[0];
    const float* rc     = (const float*)d_in[1];
    const float* rs     = (const float*)d_in[2];
    const float* qkv_w  = (const float*)d_in[3];
    const float* qkv_b  = (const float*)d_in[4];
    const float* out_w  = (const float*)d_in[5];
    const float* out_b  = (const float*)d_in[6];
    float* out = (float*)d_out;

    cudaFuncSetAttribute(k_qkv,    cudaFuncAttributeMaxDynamicSharedMemorySize, SMEM_ALL);
    cudaFuncSetAttribute(k_scores, cudaFuncAttributeMaxDynamicSharedMemorySize, SMEM_ALL);
    cudaFuncSetAttribute(k_pv,     cudaFuncAttributeMaxDynamicSharedMemorySize, SMEM_ALL);
    cudaFuncSetAttribute(k_out,    cudaFuncAttributeMaxDynamicSharedMemorySize, SMEM_ALL);

    float *px, *pw, *pwo;
    cudaGetSymbolAddress((void**)&px,  g_x);
    cudaGetSymbolAddress((void**)&pw,  g_w);
    cudaGetSymbolAddress((void**)&pwo, g_wo);

    k_round<<<2048, 256>>>((const float4*)x,     (float4*)px,  MROWS*DDIM/4);
    k_round<<<3072, 256>>>((const float4*)qkv_w, (float4*)pw,  E3*DDIM/4);
    k_round<<<1024, 256>>>((const float4*)out_w, (float4*)pwo, DDIM*DDIM/4);

    k_qkv<<<dim3(E3/128, MROWS/128), 128, SMEM_ALL>>>(qkv_b, rc, rs);
    k_scores<<<dim3(TT/128, TT/128, BH), 128, SMEM_ALL>>>();
    k_finalize<<<(BH*TT + 255)/256, 256>>>();
    k_pv<<<dim3(TT/128, BH), 128, SMEM_ALL>>>();
    k_out<<<dim3(DDIM/128, MROWS/128), 128, SMEM_ALL>>>(out_b, out);
}

// round 14
// speedup vs baseline: 1.6916x; 1.1876x over previous
#include <cuda_runtime.h>
#include <cstdint>
#include <math.h>
#include <float.h>

#define BD 2
#define TT 2048
#define DDIM 2048
#define NH 16
#define HD 128
#define BH (BD*NH)         // 32
#define MROWS (BD*TT)      // 4096
#define E3 (3*DDIM)        // 6144
#define SCALE 0.08838834764831843f

// GEMM path: CTA tile 128x128, 128 threads (4 warps 2x2), warp tile 64x64.
// K-chunk 32, pitch 144B (conflict-free ldmatrix), 3-stage cp.async pipeline.
#define P32 144
#define ASZ32 (128*P32)        // 18432
#define STG32 (2*ASZ32)        // 36864
#define SMEM_ALL (3*STG32)     // 110592 (covers 67584B qkv epilogue staging)

// ---- Flash kernel geometry: BM=128 q-rows, BN=64 kv per iter ----
// All tiles use the chunk format: chunk = rows x 144B pitch, 32 floats payload,
// within-chunk k-slice = (ks&3)*32 bytes, chunk index = ks>>2.
#define FP   144
#define QCH  (128*FP)          // 18432 (128 q-rows x 32 d)
#define KCH  (64*FP)           // 9216  (64 t-rows x 32 d)
#define KTILE (4*KCH)          // 36864 (K=128 d -> 4 chunks)
#define VCH  (128*FP)          // 18432 (128 d-rows x 32 t)
#define VTILE (2*VCH)          // 36864 (k=64 t -> 2 chunks)
#define PCH  (128*FP)          // 18432 (128 q-rows x 32 t)
#define PTILE (2*PCH)          // 36864
#define FOFF_Q 0
#define FOFF_K (4*QCH)                 // 73728, two KTILE buffers
#define FOFF_V (FOFF_K + 2*KTILE)      // 147456
#define FOFF_P (FOFF_V + VTILE)        // 184320
#define FOFF_PMAX (FOFF_P + PTILE)     // 221184, [128][4]
#define FOFF_PSUM (FOFF_PMAX + 2048)   // 223232, [128][4]
#define FOFF_M    (FOFF_PSUM + 2048)   // 225280, [128]
#define FOFF_L    (FOFF_M + 512)       // 225792, [128]
#define FSMEM     (FOFF_L + 512)       // 226304

// ------------------ scratch (static device, allocation-free) ------------------
__device__ float g_x [(size_t)MROWS*DDIM];    // tf32-rounded X
__device__ float g_w [(size_t)E3*DDIM];       // tf32-rounded qkv_w
__device__ float g_wo[(size_t)DDIM*DDIM];     // tf32-rounded out_w
__device__ float g_q[(size_t)BH*TT*HD];       // tf32-rounded (RoPE'd)
__device__ float g_k[(size_t)BH*TT*HD];
__device__ float g_vt[(size_t)BH*HD*TT];      // V transposed [bh][d][t], tf32-rounded
__device__ float g_attn[(size_t)MROWS*DDIM];  // tf32-rounded

// ------------------ helpers ------------------
static __device__ __forceinline__ uint32_t smem_u32(const void* p){
    uint32_t a;
    asm("{ .reg .u64 t; cvta.to.shared.u64 t, %1; cvt.u32.u64 %0, t; }" : "=r"(a) : "l"(p));
    return a;
}
static __device__ __forceinline__ uint32_t f2tf32(float x){
    uint32_t y; asm("cvt.rn.tf32.f32 %0, %1;" : "=r"(y) : "f"(x)); return y;
}
static __device__ __forceinline__ float rnd(float x){ return __uint_as_float(f2tf32(x)); }

static __device__ __forceinline__ void cp16(uint32_t dst, const void* src){
    uint64_t g;
    asm("cvta.to.global.u64 %0, %1;" : "=l"(g) : "l"(src));
    asm volatile("cp.async.cg.shared.global [%0], [%1], 16;" :: "r"(dst), "l"(g) : "memory");
}
#define CP_COMMIT() asm volatile("cp.async.commit_group;" ::: "memory")
#define CP_WAIT1()  asm volatile("cp.async.wait_group 1;" ::: "memory")
#define CP_WAIT2()  asm volatile("cp.async.wait_group 2;" ::: "memory")

#define LDMX4(r, addr) asm volatile( \
    "ldmatrix.sync.aligned.m8n8.x4.shared.b16 {%0,%1,%2,%3}, [%4];" \
    : "=r"((r)[0]),"=r"((r)[1]),"=r"((r)[2]),"=r"((r)[3]) : "r"(addr))

static __device__ __forceinline__ void mma8(float* c, const uint32_t* a, const uint32_t* b){
    asm volatile(
        "mma.sync.aligned.m16n8k8.row.col.f32.tf32.tf32.f32 "
        "{%0,%1,%2,%3}, {%4,%5,%6,%7}, {%8,%9}, {%0,%1,%2,%3};"
        : "+f"(c[0]), "+f"(c[1]), "+f"(c[2]), "+f"(c[3])
        : "r"(a[0]), "r"(a[1]), "r"(a[2]), "r"(a[3]), "r"(b[0]), "r"(b[1]));
}

// compute one K-chunk (NKS ks-slices of K=8): warp tile 64x64, 16*NKS MMAs
template<int NKS, int P, int ASZ>
static __device__ __forceinline__ void compute_chunk(uint32_t stg, float (&acc)[4][8][4],
                                                     int aoff, int boff)
{
    #pragma unroll
    for (int ks = 0; ks < NKS; ks++){
        uint32_t a[4][4], b[4][4];
        #pragma unroll
        for (int mi = 0; mi < 4; mi++)
            LDMX4(a[mi], stg + aoff + mi*(16*P) + ks*32);
        #pragma unroll
        for (int p = 0; p < 4; p++)
            LDMX4(b[p], stg + ASZ + boff + p*(16*P) + ks*32);
        #pragma unroll
        for (int mi = 0; mi < 4; mi++)
            #pragma unroll
            for (int p = 0; p < 4; p++){
                mma8(acc[mi][2*p],   a[mi], &b[p][0]);
                mma8(acc[mi][2*p+1], a[mi], &b[p][2]);
            }
    }
}

// cp.async loads for one K=32 chunk (A,B: 128 rows x 128B; 128 threads)
static __device__ __forceinline__ void cp_issue32(uint32_t stg,
    const float* __restrict__ A, size_t lda,
    const float* __restrict__ B, size_t ldb, int k0, int tid)
{
    const int kc = tid & 7, r0 = tid >> 3;   // 8 x 16B segments, 16 row-groups
    #pragma unroll
    for (int j = 0; j < 8; j++){
        const int r = r0 + 16*j;
        cp16(stg + r*P32 + kc*16, A + (size_t)r*lda + k0 + kc*4);
    }
    #pragma unroll
    for (int j = 0; j < 8; j++){
        const int r = r0 + 16*j;
        cp16(stg + ASZ32 + r*P32 + kc*16, B + (size_t)r*ldb + k0 + kc*4);
    }
}

// C[128,128] += A[128,K]*B[128,K]^T, K = nIter*32, 3-stage cp.async pipeline
static __device__ __forceinline__ void gemm_cp(uint32_t smb, float (&acc)[4][8][4],
    const float* __restrict__ A, size_t lda,
    const float* __restrict__ B, size_t ldb, int nIter, int aoff, int boff)
{
    const int tid = threadIdx.x;
    #pragma unroll
    for (int s = 0; s < 2; s++){
        if (s < nIter) cp_issue32(smb + s*STG32, A, lda, B, ldb, s*32, tid);
        CP_COMMIT();
    }
    int stq = 2;                    // next stage slot to fill
    for (int kt = 0; kt < nIter; kt++){
        CP_WAIT1();
        __syncthreads();
        if (kt + 2 < nIter){
            cp_issue32(smb + stq*STG32, A, lda, B, ldb, (kt+2)*32, tid);
            if (++stq == 3) stq = 0;
        }
        CP_COMMIT();
        int cur = kt % 3;
        compute_chunk<4, P32, ASZ32>(smb + cur*STG32, acc, aoff, boff);
    }
}

#define GEMM_PROLOGUE(P) \
    extern __shared__ char sm[]; \
    const uint32_t smb = smem_u32(sm); \
    const int tid = threadIdx.x; \
    const int w = tid >> 5, wm = w >> 1, wn = w & 1, l = tid & 31; \
    const int fg = l >> 2, ft = l & 3; \
    const int aoff = (wm*64 + (l&15))*(P) + ((l>>4)<<4); \
    const int boff = (wn*64 + ((l>>4)<<3) + (l&7))*(P) + (((l>>3)&1)<<4); \
    float acc[4][8][4]; \
    _Pragma("unroll") for (int mi = 0; mi < 4; mi++) \
    _Pragma("unroll") for (int ni = 0; ni < 8; ni++) \
    _Pragma("unroll") for (int j = 0; j < 4; j++) acc[mi][ni][j] = 0.f;

// ======================= pre-round inputs to tf32 bit patterns =======================
__global__ void k_round(const float4* __restrict__ src, float4* __restrict__ dst, int n4)
{
    for (int i = blockIdx.x*blockDim.x + threadIdx.x; i < n4; i += gridDim.x*blockDim.x){
        float4 v = src[i];
        dst[i] = make_float4(rnd(v.x), rnd(v.y), rnd(v.z), rnd(v.w));
    }
}

// ======================= QKV GEMM + fused bias/RoPE + V transpose =======================
__global__ __launch_bounds__(128, 2) void k_qkv(const float* __restrict__ bias,
                                                const float* __restrict__ cs,
                                                const float* __restrict__ sn)
{
    GEMM_PROLOGUE(P32);
    const int n0 = blockIdx.x * 128, m0 = blockIdx.y * 128;
    gemm_cp(smb, acc, g_x + (size_t)m0*DDIM, DDIM, g_w + (size_t)n0*DDIM, DDIM, DDIM/32,
            aoff, boff);
    __syncthreads();

    // stage tile (+bias) to smem [128][132]
    float* smC = (float*)sm;
    #pragma unroll
    for (int ni = 0; ni < 8; ni++){
        const int c = wn*64 + ni*8 + 2*ft;
        const float b0 = bias[n0 + c], b1 = bias[n0 + c + 1];
        #pragma unroll
        for (int mi = 0; mi < 4; mi++){
            const int rr = wm*64 + 16*mi + fg;
            smC[rr*132 + c]     = acc[mi][ni][0] + b0;
            smC[rr*132 + c + 1] = acc[mi][ni][1] + b1;
            smC[(rr+8)*132 + c]     = acc[mi][ni][2] + b0;
            smC[(rr+8)*132 + c + 1] = acc[mi][ni][3] + b1;
        }
    }
    __syncthreads();

    const int s = n0 >> 11, h = (n0 & 2047) >> 7;
    const int bb = m0 >> 11, t0 = m0 & 2047;
    if (s < 2){
        // RoPE: each thread owns one row, all 128 columns (pairs c, c+64)
        const int r = tid;
        const int t = t0 + r;
        float* dst = (s ? g_k : g_q) + ((size_t)(bb*NH + h)*TT + t)*HD;
        const float* csr = cs + (size_t)t*HD;
        const float* snr = sn + (size_t)t*HD;
        #pragma unroll
        for (int jj = 0; jj < 16; jj++){
            const int c = jj*4;
            float4 x1 = *(const float4*)(smC + r*132 + c);
            float4 x2 = *(const float4*)(smC + r*132 + c + 64);
            float4 c0 = *(const float4*)(csr + c);
            float4 s0 = *(const float4*)(snr + c);
            float4 c1 = *(const float4*)(csr + c + 64);
            float4 s1 = *(const float4*)(snr + c + 64);
            *(float4*)(dst + c) = make_float4(
                rnd(x1.x*c0.x - x2.x*s0.x), rnd(x1.y*c0.y - x2.y*s0.y),
                rnd(x1.z*c0.z - x2.z*s0.z), rnd(x1.w*c0.w - x2.w*s0.w));
            *(float4*)(dst + c + 64) = make_float4(
                rnd(x2.x*c1.x + x1.x*s1.x), rnd(x2.y*c1.y + x1.y*s1.y),
                rnd(x2.z*c1.z + x1.z*s1.z), rnd(x2.w*c1.w + x1.w*s1.w));
        }
    } else {
        float* dstb = g_vt + (size_t)(bb*NH + h)*HD*TT;
        #pragma unroll
        for (int i = 0; i < 32; i++){
            const int ii = tid + i*128;
            const int d = ii >> 5, tq = ii & 31;
            *(float4*)(dstb + (size_t)d*TT + t0 + tq*4) = make_float4(
                rnd(smC[(tq*4 + 0)*132 + d]), rnd(smC[(tq*4 + 1)*132 + d]),
                rnd(smC[(tq*4 + 2)*132 + d]), rnd(smC[(tq*4 + 3)*132 + d]));
        }
    }
}

// ======================= Flash attention: S=QK^T, online softmax, O=P·V =======================
// BM=128 (Q resident), BN=64 per iteration. 256 thr, 8 warps (wm 0..1 x wn 0..3).
// S warp tile 64x16; O warp tile 64x32.
__global__ __launch_bounds__(256, 1) void k_flash()
{
    extern __shared__ char sm[];
    const uint32_t smb = smem_u32(sm);
    const int tid = threadIdx.x;
    const int w = tid >> 5, l = tid & 31;
    const int wm = w >> 2, wn = w & 3;
    const int fg = l >> 2, ft = l & 3;
    const int mt = (TT/128 - 1) - blockIdx.x;   // biggest workload first
    const int bh = blockIdx.y;
    const int m0 = mt * 128;
    const int jmax = 2*mt + 1;                  // kv tiles of 64

    const uint32_t Qs = smb + FOFF_Q;
    const uint32_t Ks = smb + FOFF_K;
    const uint32_t Vs = smb + FOFF_V;
    const uint32_t Ps = smb + FOFF_P;
    float* pmax = (float*)(sm + FOFF_PMAX);  // [128][4]
    float* psum = (float*)(sm + FOFF_PSUM);  // [128][4]
    float* smM  = (float*)(sm + FOFF_M);
    float* smL  = (float*)(sm + FOFF_L);

    const int aoff  = (wm*64 + (l&15))*FP + ((l>>4)<<4);                       // A rows (q)
    const int boffS = (wn*16 + ((l>>4)<<3) + (l&7))*FP + (((l>>3)&1)<<4);      // K rows (t), 16-wide
    const int boffV = (wn*32 + ((l>>4)<<3) + (l&7))*FP + (((l>>3)&1)<<4);      // V rows (d), 32-wide

    if (tid < 128){ smM[tid] = -FLT_MAX; smL[tid] = 0.f; }

    float oacc[4][4][4];
    #pragma unroll
    for (int mi = 0; mi < 4; mi++)
        #pragma unroll
        for (int ni = 0; ni < 4; ni++)
            #pragma unroll
            for (int j = 0; j < 4; j++) oacc[mi][ni][j] = 0.f;

    const float* Qg = g_q + ((size_t)bh*TT + m0)*HD;
    const float* Kg = g_k + (size_t)bh*TT*HD;
    const float* Vg = g_vt + (size_t)bh*HD*TT;

    // K tile loader: 64 t-rows x 4 d-chunks (2048 cp16)
    auto loadK = [&](uint32_t dst, int t0){
        #pragma unroll
        for (int i = 0; i < 8; i++){
            const int idx = tid + i*256;
            const int c = idx >> 9, r = (idx >> 3) & 63, kc = idx & 7;
            cp16(dst + c*KCH + r*FP + kc*16, Kg + (size_t)(t0 + r)*HD + c*32 + kc*4);
        }
    };
    // V tile loader: 128 d-rows x 2 t-chunks (2048 cp16)
    auto loadV = [&](int t0){
        #pragma unroll
        for (int i = 0; i < 8; i++){
            const int idx = tid + i*256;
            const int c = idx >> 10, d = (idx >> 3) & 127, kc = idx & 7;
            cp16(Vs + c*VCH + d*FP + kc*16, Vg + (size_t)d*TT + t0 + c*32 + kc*4);
        }
    };

    // prologue: Q (4 chunks) + K(0)  [group 1]; K(1)  [group 2]
    #pragma unroll
    for (int i = 0; i < 16; i++){
        const int idx = tid + i*256;
        const int c = idx >> 10, r = (idx >> 3) & 127, kc = idx & 7;
        cp16(Qs + c*QCH + r*FP + kc*16, Qg + (size_t)r*HD + c*32 + kc*4);
    }
    loadK(Ks, 0);
    CP_COMMIT();
    if (jmax >= 1) loadK(Ks + KTILE, 64);
    CP_COMMIT();

    for (int jt = 0; jt <= jmax; jt++){
        // V buffer free here ([C] of previous iter). Issue V(jt); overlaps S.
        loadV(jt*64);
        CP_COMMIT();
        CP_WAIT2();                 // K(jt) complete (pending: K(jt+1), V(jt))
        __syncthreads();            // [K] K visible to all

        const uint32_t Kb = Ks + (jt & 1)*KTILE;

        // ---- S = Q·K^T (warp 64x16, K=128 over 16 ks) ----
        float sacc[4][2][4];
        #pragma unroll
        for (int mi = 0; mi < 4; mi++)
            #pragma unroll
            for (int ni = 0; ni < 2; ni++)
                #pragma unroll
                for (int j = 0; j < 4; j++) sacc[mi][ni][j] = 0.f;
        #pragma unroll
        for (int ks = 0; ks < 16; ks++){
            uint32_t a[4][4], b[4];
            #pragma unroll
            for (int mi = 0; mi < 4; mi++)
                LDMX4(a[mi], Qs + (ks>>2)*QCH + aoff + mi*(16*FP) + (ks&3)*32);
            LDMX4(b, Kb + (ks>>2)*KCH + boffS + (ks&3)*32);
            #pragma unroll
            for (int mi = 0; mi < 4; mi++){
                mma8(sacc[mi][0], a[mi], &b[0]);
                mma8(sacc[mi][1], a[mi], &b[2]);
            }
        }

        // ---- scale + causal mask + per-warp row max ----
        const int coff = jt*64 - m0;            // >=0 only on diagonal tiles
        float tm[4][2];
        #pragma unroll
        for (int mi = 0; mi < 4; mi++){ tm[mi][0] = -FLT_MAX; tm[mi][1] = -FLT_MAX; }
        #pragma unroll
        for (int mi = 0; mi < 4; mi++)
            #pragma unroll
            for (int ni = 0; ni < 2; ni++)
                #pragma unroll
                for (int j = 0; j < 4; j++){
                    float v = sacc[mi][ni][j] * SCALE;
                    if (coff >= 0){
                        const int cl = wn*16 + ni*8 + 2*ft + (j & 1);
                        const int rl = wm*64 + mi*16 + fg + 8*(j >> 1);
                        if (coff + cl > rl) v = -FLT_MAX;
                    }
                    sacc[mi][ni][j] = v;
                    tm[mi][j >> 1] = fmaxf(tm[mi][j >> 1], v);
                }
        #pragma unroll
        for (int mi = 0; mi < 4; mi++)
            #pragma unroll
            for (int hi = 0; hi < 2; hi++){
                tm[mi][hi] = fmaxf(tm[mi][hi], __shfl_xor_sync(0xffffffffu, tm[mi][hi], 1));
                tm[mi][hi] = fmaxf(tm[mi][hi], __shfl_xor_sync(0xffffffffu, tm[mi][hi], 2));
            }
        if (ft == 0){
            #pragma unroll
            for (int mi = 0; mi < 4; mi++)
                #pragma unroll
                for (int hi = 0; hi < 2; hi++)
                    pmax[(wm*64 + mi*16 + fg + 8*hi)*4 + wn] = tm[mi][hi];
        }
        __syncthreads();                        // [A] — proves S done: K(jt)'s buffer reusable

        // issue K(jt+2) into the buffer S just finished with; overlaps softmax+PV
        if (jt + 2 <= jmax) loadK(Ks + (jt & 1)*KTILE, (jt + 2)*64);
        CP_COMMIT();

        // ---- m_new, factor, P=exp, row sums ----
        float mnew[4][2], fct[4][2];
        #pragma unroll
        for (int mi = 0; mi < 4; mi++)
            #pragma unroll
            for (int hi = 0; hi < 2; hi++){
                const int r = wm*64 + mi*16 + fg + 8*hi;
                const float mo = smM[r];
                const float mx = fmaxf(fmaxf(pmax[r*4+0], pmax[r*4+1]),
                                       fmaxf(pmax[r*4+2], pmax[r*4+3]));
                const float mn = fmaxf(mo, mx);
                mnew[mi][hi] = mn;
                fct[mi][hi] = __expf(mo - mn);
            }
        float rs[4][2];
        #pragma unroll
        for (int mi = 0; mi < 4; mi++){ rs[mi][0] = 0.f; rs[mi][1] = 0.f; }
        #pragma unroll
        for (int mi = 0; mi < 4; mi++)
            #pragma unroll
            for (int ni = 0; ni < 2; ni++)
                #pragma unroll
                for (int j = 0; j < 4; j++){
                    const int hi = j >> 1;
                    const float p = __expf(sacc[mi][ni][j] - mnew[mi][hi]);
                    sacc[mi][ni][j] = p;
                    rs[mi][hi] += p;
                }
        #pragma unroll
        for (int mi = 0; mi < 4; mi++)
            #pragma unroll
            for (int hi = 0; hi < 2; hi++){
                rs[mi][hi] += __shfl_xor_sync(0xffffffffu, rs[mi][hi], 1);
                rs[mi][hi] += __shfl_xor_sync(0xffffffffu, rs[mi][hi], 2);
            }
        if (ft == 0){
            #pragma unroll
            for (int mi = 0; mi < 4; mi++)
                #pragma unroll
                for (int hi = 0; hi < 2; hi++)
                    psum[(wm*64 + mi*16 + fg + 8*hi)*4 + wn] = rs[mi][hi];
        }
        // rescale O
        #pragma unroll
        for (int mi = 0; mi < 4; mi++)
            #pragma unroll
            for (int ni = 0; ni < 4; ni++)
                #pragma unroll
                for (int j = 0; j < 4; j++)
                    oacc[mi][ni][j] *= fct[mi][j >> 1];
        // stage P (tf32-rounded, chunk format)
        #pragma unroll
        for (int mi = 0; mi < 4; mi++)
            #pragma unroll
            for (int ni = 0; ni < 2; ni++){
                const int r0 = wm*64 + mi*16 + fg;
                const int cl = wn*16 + ni*8 + 2*ft;
                const uint32_t base = Ps + (cl>>5)*PCH + (cl&31)*4;
                *(float2*)(sm + (base - smb) + (size_t)r0*FP) =
                    make_float2(rnd(sacc[mi][ni][0]), rnd(sacc[mi][ni][1]));
                *(float2*)(sm + (base - smb) + (size_t)(r0+8)*FP) =
                    make_float2(rnd(sacc[mi][ni][2]), rnd(sacc[mi][ni][3]));
            }
        CP_WAIT1();                 // V(jt) complete (pending: K(jt+2) only)
        __syncthreads();            // [B] — P and V visible

        // ---- state update (one writer per row; PV doesn't touch smM/smL) ----
        if (wn == 0 && ft == 0){
            #pragma unroll
            for (int mi = 0; mi < 4; mi++)
                #pragma unroll
                for (int hi = 0; hi < 2; hi++){
                    const int r = wm*64 + mi*16 + fg + 8*hi;
                    smL[r] = smL[r]*fct[mi][hi]
                           + (psum[r*4+0] + psum[r*4+1] + psum[r*4+2] + psum[r*4+3]);
                    smM[r] = mnew[mi][hi];
                }
        }

        // ---- O += P·V (warp 64x32 over d, k=64 t over 8 ks) ----
        #pragma unroll
        for (int ks = 0; ks < 8; ks++){
            uint32_t a[4][4], b[2][4];
            #pragma unroll
            for (int mi = 0; mi < 4; mi++)
                LDMX4(a[mi], Ps + (ks>>2)*PCH + aoff + mi*(16*FP) + (ks&3)*32);
            #pragma unroll
            for (int p = 0; p < 2; p++)
                LDMX4(b[p], Vs + (ks>>2)*VCH + boffV + p*(16*FP) + (ks&3)*32);
            #pragma unroll
            for (int mi = 0; mi < 4; mi++)
                #pragma unroll
                for (int p = 0; p < 2; p++){
                    mma8(oacc[mi][2*p],   a[mi], &b[p][0]);
                    mma8(oacc[mi][2*p+1], a[mi], &b[p][2]);
                }
        }
        __syncthreads();            // [C] — PV done; V/P buffers free for next iter
    }

    // ---- normalize + write O ----
    const int bb = bh >> 4, h = bh & 15;
    #pragma unroll
    for (int mi = 0; mi < 4; mi++){
        #pragma unroll
        for (int hi = 0; hi < 2; hi++){
            const int r = wm*64 + mi*16 + fg + 8*hi;
            const float inv = 1.f / smL[r];
            float* dst = g_attn + ((size_t)(bb*TT + m0 + r))*DDIM + h*HD;
            #pragma unroll
            for (int ni = 0; ni < 4; ni++){
                const int c = wn*32 + ni*8 + 2*ft;
                *(float2*)(dst + c) = make_float2(rnd(oacc[mi][ni][2*hi]*inv),
                                                  rnd(oacc[mi][ni][2*hi+1]*inv));
            }
        }
    }
}

// ======================= Output projection =======================
__global__ __launch_bounds__(128, 2) void k_out(const float* __restrict__ bias,
                                                float* __restrict__ Cout)
{
    GEMM_PROLOGUE(P32);
    const int n0 = blockIdx.x * 128, m0 = blockIdx.y * 128;
    gemm_cp(smb, acc, g_attn + (size_t)m0*DDIM, DDIM, g_wo + (size_t)n0*DDIM, DDIM,
            DDIM/32, aoff, boff);
    #pragma unroll
    for (int ni = 0; ni < 8; ni++){
        const int c = n0 + 64*wn + 8*ni + 2*ft;
        const float b0 = bias[c], b1 = bias[c + 1];
        #pragma unroll
        for (int mi = 0; mi < 4; mi++){
            const int m = m0 + 64*wm + 16*mi + fg;
            *(float2*)(Cout + (size_t)m*DDIM + c)     = make_float2(acc[mi][ni][0] + b0, acc[mi][ni][1] + b1);
            *(float2*)(Cout + (size_t)(m+8)*DDIM + c) = make_float2(acc[mi][ni][2] + b0, acc[mi][ni][3] + b1);
        }
    }
}

// ======================= launch =======================
extern "C" void kernel_launch(void* const* d_in, const int* in_sizes, int n_in,
                              void* d_out, int out_size)
{
    (void)in_sizes; (void)n_in; (void)out_size;
    const float* x      = (const float*)d_in[0];
    const float* rc     = (const float*)d_in[1];
    const float* rs     = (const float*)d_in[2];
    const float* qkv_w  = (const float*)d_in[3];
    const float* qkv_b  = (const float*)d_in[4];
    const float* out_w  = (const float*)d_in[5];
    const float* out_b  = (const float*)d_in[6];
    float* out = (float*)d_out;

    cudaFuncSetAttribute(k_qkv,   cudaFuncAttributeMaxDynamicSharedMemorySize, SMEM_ALL);
    cudaFuncSetAttribute(k_flash, cudaFuncAttributeMaxDynamicSharedMemorySize, FSMEM);
    cudaFuncSetAttribute(k_out,   cudaFuncAttributeMaxDynamicSharedMemorySize, SMEM_ALL);

    float *px, *pw, *pwo;
    cudaGetSymbolAddress((void**)&px,  g_x);
    cudaGetSymbolAddress((void**)&pw,  g_w);
    cudaGetSymbolAddress((void**)&pwo, g_wo);

    k_round<<<2048, 256>>>((const float4*)x,     (float4*)px,  MROWS*DDIM/4);
    k_round<<<3072, 256>>>((const float4*)qkv_w, (float4*)pw,  E3*DDIM/4);
    k_round<<<1024, 256>>>((const float4*)out_w, (float4*)pwo, DDIM*DDIM/4);

    k_qkv<<<dim3(E3/128, MROWS/128), 128, SMEM_ALL>>>(qkv_b, rc, rs);
    k_flash<<<dim3(TT/128, BH), 256, FSMEM>>>();
    k_out<<<dim3(DDIM/128, MROWS/128), 128, SMEM_ALL>>>(out_b, out);
}

// round 15
// speedup vs baseline: 1.7052x; 1.0080x over previous
#include <cuda_runtime.h>
#include <cstdint>
#include <math.h>
#include <float.h>

#define BD 2
#define TT 2048
#define DDIM 2048
#define NH 16
#define HD 128
#define BH (BD*NH)         // 32
#define MROWS (BD*TT)      // 4096
#define E3 (3*DDIM)        // 6144
#define SCALE 0.08838834764831843f

// Projection GEMMs: CTA tile 128x128, 256 threads (8 warps 2x4), warp tile 64x32.
// K-chunk 32, pitch 144B (conflict-free ldmatrix), 3-stage cp.async pipeline.
#define P32 144
#define ASZ32 (128*P32)        // 18432
#define STG32 (2*ASZ32)        // 36864
#define SMEM_ALL (3*STG32)     // 110592 (covers 67584B qkv epilogue staging)

// ---- Flash kernel geometry (unchanged from R14) ----
#define FP   144
#define QCH  (128*FP)
#define KCH  (64*FP)
#define KTILE (4*KCH)
#define VCH  (128*FP)
#define VTILE (2*VCH)
#define PCH  (128*FP)
#define PTILE (2*PCH)
#define FOFF_Q 0
#define FOFF_K (4*QCH)
#define FOFF_V (FOFF_K + 2*KTILE)
#define FOFF_P (FOFF_V + VTILE)
#define FOFF_PMAX (FOFF_P + PTILE)
#define FOFF_PSUM (FOFF_PMAX + 2048)
#define FOFF_M    (FOFF_PSUM + 2048)
#define FOFF_L    (FOFF_M + 512)
#define FSMEM     (FOFF_L + 512)       // 226304

// ------------------ scratch (static device, allocation-free) ------------------
__device__ float g_x [(size_t)MROWS*DDIM];    // tf32-rounded X
__device__ float g_w [(size_t)E3*DDIM];       // tf32-rounded qkv_w
__device__ float g_wo[(size_t)DDIM*DDIM];     // tf32-rounded out_w
__device__ float g_q[(size_t)BH*TT*HD];       // tf32-rounded (RoPE'd)
__device__ float g_k[(size_t)BH*TT*HD];
__device__ float g_vt[(size_t)BH*HD*TT];      // V transposed [bh][d][t], tf32-rounded
__device__ float g_attn[(size_t)MROWS*DDIM];  // tf32-rounded

// ------------------ helpers ------------------
static __device__ __forceinline__ uint32_t smem_u32(const void* p){
    uint32_t a;
    asm("{ .reg .u64 t; cvta.to.shared.u64 t, %1; cvt.u32.u64 %0, t; }" : "=r"(a) : "l"(p));
    return a;
}
static __device__ __forceinline__ uint32_t f2tf32(float x){
    uint32_t y; asm("cvt.rn.tf32.f32 %0, %1;" : "=r"(y) : "f"(x)); return y;
}
static __device__ __forceinline__ float rnd(float x){ return __uint_as_float(f2tf32(x)); }

static __device__ __forceinline__ void cp16(uint32_t dst, const void* src){
    uint64_t g;
    asm("cvta.to.global.u64 %0, %1;" : "=l"(g) : "l"(src));
    asm volatile("cp.async.cg.shared.global [%0], [%1], 16;" :: "r"(dst), "l"(g) : "memory");
}
#define CP_COMMIT() asm volatile("cp.async.commit_group;" ::: "memory")
#define CP_WAIT1()  asm volatile("cp.async.wait_group 1;" ::: "memory")
#define CP_WAIT2()  asm volatile("cp.async.wait_group 2;" ::: "memory")

#define LDMX4(r, addr) asm volatile( \
    "ldmatrix.sync.aligned.m8n8.x4.shared.b16 {%0,%1,%2,%3}, [%4];" \
    : "=r"((r)[0]),"=r"((r)[1]),"=r"((r)[2]),"=r"((r)[3]) : "r"(addr))

static __device__ __forceinline__ void mma8(float* c, const uint32_t* a, const uint32_t* b){
    asm volatile(
        "mma.sync.aligned.m16n8k8.row.col.f32.tf32.tf32.f32 "
        "{%0,%1,%2,%3}, {%4,%5,%6,%7}, {%8,%9}, {%0,%1,%2,%3};"
        : "+f"(c[0]), "+f"(c[1]), "+f"(c[2]), "+f"(c[3])
        : "r"(a[0]), "r"(a[1]), "r"(a[2]), "r"(a[3]), "r"(b[0]), "r"(b[1]));
}

// compute one K=32 chunk: warp tile 64x32, 64 MMAs
static __device__ __forceinline__ void compute32(uint32_t stg, float (&acc)[4][4][4],
                                                 int aoff, int boff)
{
    #pragma unroll
    for (int ks = 0; ks < 4; ks++){
        uint32_t a[4][4], b[2][4];
        #pragma unroll
        for (int mi = 0; mi < 4; mi++)
            LDMX4(a[mi], stg + aoff + mi*(16*P32) + ks*32);
        #pragma unroll
        for (int p = 0; p < 2; p++)
            LDMX4(b[p], stg + ASZ32 + boff + p*(16*P32) + ks*32);
        #pragma unroll
        for (int mi = 0; mi < 4; mi++)
            #pragma unroll
            for (int p = 0; p < 2; p++){
                mma8(acc[mi][2*p],   a[mi], &b[p][0]);
                mma8(acc[mi][2*p+1], a[mi], &b[p][2]);
            }
    }
}

// cp.async loads for one K=32 chunk (A,B: 128 rows x 128B; 256 threads)
static __device__ __forceinline__ void cp_issue32(uint32_t stg,
    const float* __restrict__ A, size_t lda,
    const float* __restrict__ B, size_t ldb, int k0, int tid)
{
    #pragma unroll
    for (int i = 0; i < 4; i++){
        const int idx = tid + i*256;
        const int r = idx >> 3, kc = idx & 7;
        cp16(stg + r*P32 + kc*16, A + (size_t)r*lda + k0 + kc*4);
    }
    #pragma unroll
    for (int i = 0; i < 4; i++){
        const int idx = tid + i*256;
        const int r = idx >> 3, kc = idx & 7;
        cp16(stg + ASZ32 + r*P32 + kc*16, B + (size_t)r*ldb + k0 + kc*4);
    }
}

// C[128,128] += A[128,K]*B[128,K]^T, K = nIter*32, 3-stage cp.async pipeline
static __device__ __forceinline__ void gemm_cp(uint32_t smb, float (&acc)[4][4][4],
    const float* __restrict__ A, size_t lda,
    const float* __restrict__ B, size_t ldb, int nIter, int aoff, int boff)
{
    const int tid = threadIdx.x;
    #pragma unroll
    for (int s = 0; s < 2; s++){
        if (s < nIter) cp_issue32(smb + s*STG32, A, lda, B, ldb, s*32, tid);
        CP_COMMIT();
    }
    int stq = 2;
    for (int kt = 0; kt < nIter; kt++){
        CP_WAIT1();
        __syncthreads();
        if (kt + 2 < nIter){
            cp_issue32(smb + stq*STG32, A, lda, B, ldb, (kt+2)*32, tid);
            if (++stq == 3) stq = 0;
        }
        CP_COMMIT();
        compute32(smb + (kt % 3)*STG32, acc, aoff, boff);
    }
}

#define GEMM_PROLOGUE() \
    extern __shared__ char sm[]; \
    const uint32_t smb = smem_u32(sm); \
    const int tid = threadIdx.x; \
    const int w = tid >> 5, wm = w >> 2, wn = w & 3, l = tid & 31; \
    const int fg = l >> 2, ft = l & 3; \
    const int aoff = (wm*64 + (l&15))*P32 + ((l>>4)<<4); \
    const int boff = (wn*32 + ((l>>4)<<3) + (l&7))*P32 + (((l>>3)&1)<<4); \
    float acc[4][4][4]; \
    _Pragma("unroll") for (int mi = 0; mi < 4; mi++) \
    _Pragma("unroll") for (int ni = 0; ni < 4; ni++) \
    _Pragma("unroll") for (int j = 0; j < 4; j++) acc[mi][ni][j] = 0.f;

// ======================= pre-round inputs to tf32 bit patterns =======================
__global__ void k_round(const float4* __restrict__ src, float4* __restrict__ dst, int n4)
{
    for (int i = blockIdx.x*blockDim.x + threadIdx.x; i < n4; i += gridDim.x*blockDim.x){
        float4 v = src[i];
        dst[i] = make_float4(rnd(v.x), rnd(v.y), rnd(v.z), rnd(v.w));
    }
}

// ======================= QKV GEMM + fused bias/RoPE + V transpose =======================
__global__ __launch_bounds__(256, 2) void k_qkv(const float* __restrict__ bias,
                                                const float* __restrict__ cs,
                                                const float* __restrict__ sn)
{
    GEMM_PROLOGUE();
    const int n0 = blockIdx.x * 128, m0 = blockIdx.y * 128;
    gemm_cp(smb, acc, g_x + (size_t)m0*DDIM, DDIM, g_w + (size_t)n0*DDIM, DDIM, DDIM/32,
            aoff, boff);
    __syncthreads();

    // stage tile (+bias) to smem [128][132]
    float* smC = (float*)sm;
    #pragma unroll
    for (int ni = 0; ni < 4; ni++){
        const int c = wn*32 + ni*8 + 2*ft;
        const float b0 = bias[n0 + c], b1 = bias[n0 + c + 1];
        #pragma unroll
        for (int mi = 0; mi < 4; mi++){
            const int rr = wm*64 + 16*mi + fg;
            smC[rr*132 + c]     = acc[mi][ni][0] + b0;
            smC[rr*132 + c + 1] = acc[mi][ni][1] + b1;
            smC[(rr+8)*132 + c]     = acc[mi][ni][2] + b0;
            smC[(rr+8)*132 + c + 1] = acc[mi][ni][3] + b1;
        }
    }
    __syncthreads();

    const int s = n0 >> 11, h = (n0 & 2047) >> 7;
    const int bb = m0 >> 11, t0 = m0 & 2047;
    if (s < 2){
        // RoPE: r = tid&127 owns row, half = tid>>7 owns 32 of 64 column-pairs
        const int r = tid & 127, half = tid >> 7;
        const int t = t0 + r;
        float* dst = (s ? g_k : g_q) + ((size_t)(bb*NH + h)*TT + t)*HD;
        const float* csr = cs + (size_t)t*HD;
        const float* snr = sn + (size_t)t*HD;
        #pragma unroll
        for (int jj = 0; jj < 8; jj++){
            const int c = half*32 + jj*4;
            float4 x1 = *(const float4*)(smC + r*132 + c);
            float4 x2 = *(const float4*)(smC + r*132 + c + 64);
            float4 c0 = *(const float4*)(csr + c);
            float4 s0 = *(const float4*)(snr + c);
            float4 c1 = *(const float4*)(csr + c + 64);
            float4 s1 = *(const float4*)(snr + c + 64);
            *(float4*)(dst + c) = make_float4(
                rnd(x1.x*c0.x - x2.x*s0.x), rnd(x1.y*c0.y - x2.y*s0.y),
                rnd(x1.z*c0.z - x2.z*s0.z), rnd(x1.w*c0.w - x2.w*s0.w));
            *(float4*)(dst + c + 64) = make_float4(
                rnd(x2.x*c1.x + x1.x*s1.x), rnd(x2.y*c1.y + x1.y*s1.y),
                rnd(x2.z*c1.z + x1.z*s1.z), rnd(x2.w*c1.w + x1.w*s1.w));
        }
    } else {
        float* dstb = g_vt + (size_t)(bb*NH + h)*HD*TT;
        #pragma unroll
        for (int i = 0; i < 16; i++){
            const int ii = tid + i*256;
            const int d = ii >> 5, tq = ii & 31;
            *(float4*)(dstb + (size_t)d*TT + t0 + tq*4) = make_float4(
                rnd(smC[(tq*4 + 0)*132 + d]), rnd(smC[(tq*4 + 1)*132 + d]),
                rnd(smC[(tq*4 + 2)*132 + d]), rnd(smC[(tq*4 + 3)*132 + d]));
        }
    }
}

// ======================= Flash attention (unchanged from R14) =======================
__global__ __launch_bounds__(256, 1) void k_flash()
{
    extern __shared__ char sm[];
    const uint32_t smb = smem_u32(sm);
    const int tid = threadIdx.x;
    const int w = tid >> 5, l = tid & 31;
    const int wm = w >> 2, wn = w & 3;
    const int fg = l >> 2, ft = l & 3;
    const int mt = (TT/128 - 1) - blockIdx.x;
    const int bh = blockIdx.y;
    const int m0 = mt * 128;
    const int jmax = 2*mt + 1;

    const uint32_t Qs = smb + FOFF_Q;
    const uint32_t Ks = smb + FOFF_K;
    const uint32_t Vs = smb + FOFF_V;
    const uint32_t Ps = smb + FOFF_P;
    float* pmax = (float*)(sm + FOFF_PMAX);
    float* psum = (float*)(sm + FOFF_PSUM);
    float* smM  = (float*)(sm + FOFF_M);
    float* smL  = (float*)(sm + FOFF_L);

    const int aoff  = (wm*64 + (l&15))*FP + ((l>>4)<<4);
    const int boffS = (wn*16 + ((l>>4)<<3) + (l&7))*FP + (((l>>3)&1)<<4);
    const int boffV = (wn*32 + ((l>>4)<<3) + (l&7))*FP + (((l>>3)&1)<<4);

    if (tid < 128){ smM[tid] = -FLT_MAX; smL[tid] = 0.f; }

    float oacc[4][4][4];
    #pragma unroll
    for (int mi = 0; mi < 4; mi++)
        #pragma unroll
        for (int ni = 0; ni < 4; ni++)
            #pragma unroll
            for (int j = 0; j < 4; j++) oacc[mi][ni][j] = 0.f;

    const float* Qg = g_q + ((size_t)bh*TT + m0)*HD;
    const float* Kg = g_k + (size_t)bh*TT*HD;
    const float* Vg = g_vt + (size_t)bh*HD*TT;

    auto loadK = [&](uint32_t dst, int t0){
        #pragma unroll
        for (int i = 0; i < 8; i++){
            const int idx = tid + i*256;
            const int c = idx >> 9, r = (idx >> 3) & 63, kc = idx & 7;
            cp16(dst + c*KCH + r*FP + kc*16, Kg + (size_t)(t0 + r)*HD + c*32 + kc*4);
        }
    };
    auto loadV = [&](int t0){
        #pragma unroll
        for (int i = 0; i < 8; i++){
            const int idx = tid + i*256;
            const int c = idx >> 10, d = (idx >> 3) & 127, kc = idx & 7;
            cp16(Vs + c*VCH + d*FP + kc*16, Vg + (size_t)d*TT + t0 + c*32 + kc*4);
        }
    };

    #pragma unroll
    for (int i = 0; i < 16; i++){
        const int idx = tid + i*256;
        const int c = idx >> 10, r = (idx >> 3) & 127, kc = idx & 7;
        cp16(Qs + c*QCH + r*FP + kc*16, Qg + (size_t)r*HD + c*32 + kc*4);
    }
    loadK(Ks, 0);
    CP_COMMIT();
    if (jmax >= 1) loadK(Ks + KTILE, 64);
    CP_COMMIT();

    for (int jt = 0; jt <= jmax; jt++){
        loadV(jt*64);
        CP_COMMIT();
        CP_WAIT2();
        __syncthreads();

        const uint32_t Kb = Ks + (jt & 1)*KTILE;

        float sacc[4][2][4];
        #pragma unroll
        for (int mi = 0; mi < 4; mi++)
            #pragma unroll
            for (int ni = 0; ni < 2; ni++)
                #pragma unroll
                for (int j = 0; j < 4; j++) sacc[mi][ni][j] = 0.f;
        #pragma unroll
        for (int ks = 0; ks < 16; ks++){
            uint32_t a[4][4], b[4];
            #pragma unroll
            for (int mi = 0; mi < 4; mi++)
                LDMX4(a[mi], Qs + (ks>>2)*QCH + aoff + mi*(16*FP) + (ks&3)*32);
            LDMX4(b, Kb + (ks>>2)*KCH + boffS + (ks&3)*32);
            #pragma unroll
            for (int mi = 0; mi < 4; mi++){
                mma8(sacc[mi][0], a[mi], &b[0]);
                mma8(sacc[mi][1], a[mi], &b[2]);
            }
        }

        const int coff = jt*64 - m0;
        float tm[4][2];
        #pragma unroll
        for (int mi = 0; mi < 4; mi++){ tm[mi][0] = -FLT_MAX; tm[mi][1] = -FLT_MAX; }
        #pragma unroll
        for (int mi = 0; mi < 4; mi++)
            #pragma unroll
            for (int ni = 0; ni < 2; ni++)
                #pragma unroll
                for (int j = 0; j < 4; j++){
                    float v = sacc[mi][ni][j] * SCALE;
                    if (coff >= 0){
                        const int cl = wn*16 + ni*8 + 2*ft + (j & 1);
                        const int rl = wm*64 + mi*16 + fg + 8*(j >> 1);
                        if (coff + cl > rl) v = -FLT_MAX;
                    }
                    sacc[mi][ni][j] = v;
                    tm[mi][j >> 1] = fmaxf(tm[mi][j >> 1], v);
                }
        #pragma unroll
        for (int mi = 0; mi < 4; mi++)
            #pragma unroll
            for (int hi = 0; hi < 2; hi++){
                tm[mi][hi] = fmaxf(tm[mi][hi], __shfl_xor_sync(0xffffffffu, tm[mi][hi], 1));
                tm[mi][hi] = fmaxf(tm[mi][hi], __shfl_xor_sync(0xffffffffu, tm[mi][hi], 2));
            }
        if (ft == 0){
            #pragma unroll
            for (int mi = 0; mi < 4; mi++)
                #pragma unroll
                for (int hi = 0; hi < 2; hi++)
                    pmax[(wm*64 + mi*16 + fg + 8*hi)*4 + wn] = tm[mi][hi];
        }
        __syncthreads();

        if (jt + 2 <= jmax) loadK(Ks + (jt & 1)*KTILE, (jt + 2)*64);
        CP_COMMIT();

        float mnew[4][2], fct[4][2];
        #pragma unroll
        for (int mi = 0; mi < 4; mi++)
            #pragma unroll
            for (int hi = 0; hi < 2; hi++){
                const int r = wm*64 + mi*16 + fg + 8*hi;
                const float mo = smM[r];
                const float mx = fmaxf(fmaxf(pmax[r*4+0], pmax[r*4+1]),
                                       fmaxf(pmax[r*4+2], pmax[r*4+3]));
                const float mn = fmaxf(mo, mx);
                mnew[mi][hi] = mn;
                fct[mi][hi] = __expf(mo - mn);
            }
        float rs[4][2];
        #pragma unroll
        for (int mi = 0; mi < 4; mi++){ rs[mi][0] = 0.f; rs[mi][1] = 0.f; }
        #pragma unroll
        for (int mi = 0; mi < 4; mi++)
            #pragma unroll
            for (int ni = 0; ni < 2; ni++)
                #pragma unroll
                for (int j = 0; j < 4; j++){
                    const int hi = j >> 1;
                    const float p = __expf(sacc[mi][ni][j] - mnew[mi][hi]);
                    sacc[mi][ni][j] = p;
                    rs[mi][hi] += p;
                }
        #pragma unroll
        for (int mi = 0; mi < 4; mi++)
            #pragma unroll
            for (int hi = 0; hi < 2; hi++){
                rs[mi][hi] += __shfl_xor_sync(0xffffffffu, rs[mi][hi], 1);
                rs[mi][hi] += __shfl_xor_sync(0xffffffffu, rs[mi][hi], 2);
            }
        if (ft == 0){
            #pragma unroll
            for (int mi = 0; mi < 4; mi++)
                #pragma unroll
                for (int hi = 0; hi < 2; hi++)
                    psum[(wm*64 + mi*16 + fg + 8*hi)*4 + wn] = rs[mi][hi];
        }
        #pragma unroll
        for (int mi = 0; mi < 4; mi++)
            #pragma unroll
            for (int ni = 0; ni < 4; ni++)
                #pragma unroll
                for (int j = 0; j < 4; j++)
                    oacc[mi][ni][j] *= fct[mi][j >> 1];
        #pragma unroll
        for (int mi = 0; mi < 4; mi++)
            #pragma unroll
            for (int ni = 0; ni < 2; ni++){
                const int r0 = wm*64 + mi*16 + fg;
                const int cl = wn*16 + ni*8 + 2*ft;
                const uint32_t base = Ps + (cl>>5)*PCH + (cl&31)*4;
                *(float2*)(sm + (base - smb) + (size_t)r0*FP) =
                    make_float2(rnd(sacc[mi][ni][0]), rnd(sacc[mi][ni][1]));
                *(float2*)(sm + (base - smb) + (size_t)(r0+8)*FP) =
                    make_float2(rnd(sacc[mi][ni][2]), rnd(sacc[mi][ni][3]));
            }
        CP_WAIT1();
        __syncthreads();

        if (wn == 0 && ft == 0){
            #pragma unroll
            for (int mi = 0; mi < 4; mi++)
                #pragma unroll
                for (int hi = 0; hi < 2; hi++){
                    const int r = wm*64 + mi*16 + fg + 8*hi;
                    smL[r] = smL[r]*fct[mi][hi]
                           + (psum[r*4+0] + psum[r*4+1] + psum[r*4+2] + psum[r*4+3]);
                    smM[r] = mnew[mi][hi];
                }
        }

        #pragma unroll
        for (int ks = 0; ks < 8; ks++){
            uint32_t a[4][4], b[2][4];
            #pragma unroll
            for (int mi = 0; mi < 4; mi++)
                LDMX4(a[mi], Ps + (ks>>2)*PCH + aoff + mi*(16*FP) + (ks&3)*32);
            #pragma unroll
            for (int p = 0; p < 2; p++)
                LDMX4(b[p], Vs + (ks>>2)*VCH + boffV + p*(16*FP) + (ks&3)*32);
            #pragma unroll
            for (int mi = 0; mi < 4; mi++)
                #pragma unroll
                for (int p = 0; p < 2; p++){
                    mma8(oacc[mi][2*p],   a[mi], &b[p][0]);
                    mma8(oacc[mi][2*p+1], a[mi], &b[p][2]);
                }
        }
        __syncthreads();
    }

    const int bb = bh >> 4, h = bh & 15;
    #pragma unroll
    for (int mi = 0; mi < 4; mi++){
        #pragma unroll
        for (int hi = 0; hi < 2; hi++){
            const int r = wm*64 + mi*16 + fg + 8*hi;
            const float inv = 1.f / smL[r];
            float* dst = g_attn + ((size_t)(bb*TT + m0 + r))*DDIM + h*HD;
            #pragma unroll
            for (int ni = 0; ni < 4; ni++){
                const int c = wn*32 + ni*8 + 2*ft;
                *(float2*)(dst + c) = make_float2(rnd(oacc[mi][ni][2*hi]*inv),
                                                  rnd(oacc[mi][ni][2*hi+1]*inv));
            }
        }
    }
}

// ======================= Output projection =======================
__global__ __launch_bounds__(256, 2) void k_out(const float* __restrict__ bias,
                                                float* __restrict__ Cout)
{
    GEMM_PROLOGUE();
    const int n0 = blockIdx.x * 128, m0 = blockIdx.y * 128;
    gemm_cp(smb, acc, g_attn + (size_t)m0*DDIM, DDIM, g_wo + (size_t)n0*DDIM, DDIM,
            DDIM/32, aoff, boff);
    #pragma unroll
    for (int ni = 0; ni < 4; ni++){
        const int c = n0 + wn*32 + ni*8 + 2*ft;
        const float b0 = bias[c], b1 = bias[c + 1];
        #pragma unroll
        for (int mi = 0; mi < 4; mi++){
            const int m = m0 + 64*wm + 16*mi + fg;
            *(float2*)(Cout + (size_t)m*DDIM + c)     = make_float2(acc[mi][ni][0] + b0, acc[mi][ni][1] + b1);
            *(float2*)(Cout + (size_t)(m+8)*DDIM + c) = make_float2(acc[mi][ni][2] + b0, acc[mi][ni][3] + b1);
        }
    }
}

// ======================= launch =======================
extern "C" void kernel_launch(void* const* d_in, const int* in_sizes, int n_in,
                              void* d_out, int out_size)
{
    (void)in_sizes; (void)n_in; (void)out_size;
    const float* x      = (const float*)d_in[0];
    const float* rc     = (const float*)d_in[1];
    const float* rs     = (const float*)d_in[2];
    const float* qkv_w  = (const float*)d_in[3];
    const float* qkv_b  = (const float*)d_in[4];
    const float* out_w  = (const float*)d_in[5];
    const float* out_b  = (const float*)d_in[6];
    float* out = (float*)d_out;

    cudaFuncSetAttribute(k_qkv,   cudaFuncAttributeMaxDynamicSharedMemorySize, SMEM_ALL);
    cudaFuncSetAttribute(k_flash, cudaFuncAttributeMaxDynamicSharedMemorySize, FSMEM);
    cudaFuncSetAttribute(k_out,   cudaFuncAttributeMaxDynamicSharedMemorySize, SMEM_ALL);

    float *px, *pw, *pwo;
    cudaGetSymbolAddress((void**)&px,  g_x);
    cudaGetSymbolAddress((void**)&pw,  g_w);
    cudaGetSymbolAddress((void**)&pwo, g_wo);

    k_round<<<2048, 256>>>((const float4*)x,     (float4*)px,  MROWS*DDIM/4);
    k_round<<<3072, 256>>>((const float4*)qkv_w, (float4*)pw,  E3*DDIM/4);
    k_round<<<1024, 256>>>((const float4*)out_w, (float4*)pwo, DDIM*DDIM/4);

    k_qkv<<<dim3(E3/128, MROWS/128), 256, SMEM_ALL>>>(qkv_b, rc, rs);
    k_flash<<<dim3(TT/128, BH), 256, FSMEM>>>();
    k_out<<<dim3(DDIM/128, MROWS/128), 256, SMEM_ALL>>>(out_b, out);
}

// round 16
// speedup vs baseline: 2.6574x; 1.5585x over previous
#include <cuda_runtime.h>
#include <cuda_fp16.h>
#include <cstdint>
#include <math.h>
#include <float.h>

#define BD 2
#define TT 2048
#define DDIM 2048
#define NH 16
#define HD 128
#define BH (BD*NH)         // 32
#define MROWS (BD*TT)      // 4096
#define E3 (3*DDIM)        // 6144
#define SCALE 0.08838834764831843f

// Projection GEMMs: CTA 128x128, 128 thr (4 warps 2x2), warp tile 64x64.
// fp16 m16n8k16; K-chunk 64 halves (128B rows), pitch 144B; 3-stage cp.async.
#define P32 144
#define ASZ32 (128*P32)        // 18432
#define STG32 (2*ASZ32)        // 36864
#define SMEM_ALL (3*STG32)     // 110592 (covers 67584B qkv epilogue staging)

// ---- Flash geometry (fp16): BM=128, BN=64 ----
#define FP   144
#define QCH  (128*FP)              // one 64-d chunk of Q (128 rows)
#define KCH  (64*FP)               // one 64-d chunk of K (64 rows)
#define KTILE (2*KCH)              // d=128 -> 2 chunks
#define VTILE (128*FP)             // V: 128 d-rows x 64 t halves (1 chunk)
#define PTILE (128*FP)             // P: 128 q-rows x 64 t halves (1 chunk)
#define FOFF_Q 0
#define FOFF_K (2*QCH)                 // 36864
#define FOFF_V (FOFF_K + 2*KTILE)      // 73728
#define FOFF_P (FOFF_V + VTILE)        // 92160
#define FOFF_PMAX (FOFF_P + PTILE)     // 110592
#define FOFF_PSUM (FOFF_PMAX + 2048)
#define FOFF_M    (FOFF_PSUM + 2048)
#define FOFF_L    (FOFF_M + 512)
#define FSMEM     (FOFF_L + 512)       // 115712

// ------------------ scratch (static device, allocation-free) ------------------
__device__ __half g_x [(size_t)MROWS*DDIM];
__device__ __half g_w [(size_t)E3*DDIM];
__device__ __half g_wo[(size_t)DDIM*DDIM];
__device__ __half g_q [(size_t)BH*TT*HD];
__device__ __half g_k [(size_t)BH*TT*HD];
__device__ __half g_vt[(size_t)BH*HD*TT];     // V transposed [bh][d][t]
__device__ __half g_attn[(size_t)MROWS*DDIM];

// ------------------ helpers ------------------
static __device__ __forceinline__ uint32_t smem_u32(const void* p){
    uint32_t a;
    asm("{ .reg .u64 t; cvta.to.shared.u64 t, %1; cvt.u32.u64 %0, t; }" : "=r"(a) : "l"(p));
    return a;
}
static __device__ __forceinline__ uint2 h4(float a, float b, float c, float d){
    __half2 lo = __floats2half2_rn(a, b), hi = __floats2half2_rn(c, d);
    uint2 u; u.x = *(uint32_t*)&lo; u.y = *(uint32_t*)&hi; return u;
}

static __device__ __forceinline__ void cp16(uint32_t dst, const void* src){
    uint64_t g;
    asm("cvta.to.global.u64 %0, %1;" : "=l"(g) : "l"(src));
    asm volatile("cp.async.cg.shared.global [%0], [%1], 16;" :: "r"(dst), "l"(g) : "memory");
}
#define CP_COMMIT() asm volatile("cp.async.commit_group;" ::: "memory")
#define CP_WAIT1()  asm volatile("cp.async.wait_group 1;" ::: "memory")
#define CP_WAIT2()  asm volatile("cp.async.wait_group 2;" ::: "memory")

#define LDMX4(r, addr) asm volatile( \
    "ldmatrix.sync.aligned.m8n8.x4.shared.b16 {%0,%1,%2,%3}, [%4];" \
    : "=r"((r)[0]),"=r"((r)[1]),"=r"((r)[2]),"=r"((r)[3]) : "r"(addr))

// fp16 m16n8k16, fp32 accum
static __device__ __forceinline__ void mma16(float* c, const uint32_t* a,
                                             uint32_t b0, uint32_t b1){
    asm volatile(
        "mma.sync.aligned.m16n8k16.row.col.f32.f16.f16.f32 "
        "{%0,%1,%2,%3}, {%4,%5,%6,%7}, {%8,%9}, {%0,%1,%2,%3};"
        : "+f"(c[0]), "+f"(c[1]), "+f"(c[2]), "+f"(c[3])
        : "r"(a[0]), "r"(a[1]), "r"(a[2]), "r"(a[3]), "r"(b0), "r"(b1));
}

// compute one K=64 chunk: warp tile 64x64, 4 k16 slices, 32 MMAs each
static __device__ __forceinline__ void compute64(uint32_t stg, float (&acc)[4][8][4],
                                                 int aoff, int boff)
{
    #pragma unroll
    for (int ks = 0; ks < 4; ks++){
        uint32_t a[4][4], b[4][4];
        #pragma unroll
        for (int mi = 0; mi < 4; mi++)
            LDMX4(a[mi], stg + aoff + mi*(16*P32) + ks*32);
        #pragma unroll
        for (int p = 0; p < 4; p++)
            LDMX4(b[p], stg + ASZ32 + boff + p*(16*P32) + ks*32);
        #pragma unroll
        for (int mi = 0; mi < 4; mi++)
            #pragma unroll
            for (int p = 0; p < 4; p++){
                mma16(acc[mi][2*p],   a[mi], b[p][0], b[p][2]);
                mma16(acc[mi][2*p+1], a[mi], b[p][1], b[p][3]);
            }
    }
}

// cp.async loads for one K=64-half chunk (A,B: 128 rows x 128B; 128 threads)
static __device__ __forceinline__ void cp_issue64(uint32_t stg,
    const __half* __restrict__ A, size_t lda,
    const __half* __restrict__ B, size_t ldb, int k0, int tid)
{
    const int kc = tid & 7, r0 = tid >> 3;
    #pragma unroll
    for (int j = 0; j < 8; j++){
        const int r = r0 + 16*j;
        cp16(stg + r*P32 + kc*16, A + (size_t)r*lda + k0 + kc*8);
    }
    #pragma unroll
    for (int j = 0; j < 8; j++){
        const int r = r0 + 16*j;
        cp16(stg + ASZ32 + r*P32 + kc*16, B + (size_t)r*ldb + k0 + kc*8);
    }
}

// C[128,128] += A[128,K]*B[128,K]^T (fp16), K = nIter*64, 3-stage pipeline
static __device__ __forceinline__ void gemm_cp(uint32_t smb, float (&acc)[4][8][4],
    const __half* __restrict__ A, size_t lda,
    const __half* __restrict__ B, size_t ldb, int nIter, int aoff, int boff)
{
    const int tid = threadIdx.x;
    #pragma unroll
    for (int s = 0; s < 2; s++){
        if (s < nIter) cp_issue64(smb + s*STG32, A, lda, B, ldb, s*64, tid);
        CP_COMMIT();
    }
    int stq = 2;
    for (int kt = 0; kt < nIter; kt++){
        CP_WAIT1();
        __syncthreads();
        if (kt + 2 < nIter){
            cp_issue64(smb + stq*STG32, A, lda, B, ldb, (kt+2)*64, tid);
            if (++stq == 3) stq = 0;
        }
        CP_COMMIT();
        compute64(smb + (kt % 3)*STG32, acc, aoff, boff);
    }
}

#define GEMM_PROLOGUE() \
    extern __shared__ char sm[]; \
    const uint32_t smb = smem_u32(sm); \
    const int tid = threadIdx.x; \
    const int w = tid >> 5, wm = w >> 1, wn = w & 1, l = tid & 31; \
    const int fg = l >> 2, ft = l & 3; \
    const int aoff = (wm*64 + (l&15))*P32 + ((l>>4)<<4); \
    const int boff = (wn*64 + (l&15))*P32 + ((l>>4)<<4); \
    float acc[4][8][4]; \
    _Pragma("unroll") for (int mi = 0; mi < 4; mi++) \
    _Pragma("unroll") for (int ni = 0; ni < 8; ni++) \
    _Pragma("unroll") for (int j = 0; j < 4; j++) acc[mi][ni][j] = 0.f;

// ======================= convert fp32 inputs to fp16 =======================
__global__ void k_half(const float4* __restrict__ src, uint2* __restrict__ dst, int n4)
{
    for (int i = blockIdx.x*blockDim.x + threadIdx.x; i < n4; i += gridDim.x*blockDim.x){
        float4 v = src[i];
        dst[i] = h4(v.x, v.y, v.z, v.w);
    }
}

// ======================= QKV GEMM + fused bias/RoPE + V transpose =======================
__global__ __launch_bounds__(128, 2) void k_qkv(const float* __restrict__ bias,
                                                const float* __restrict__ cs,
                                                const float* __restrict__ sn)
{
    GEMM_PROLOGUE();
    const int n0 = blockIdx.x * 128, m0 = blockIdx.y * 128;
    gemm_cp(smb, acc, g_x + (size_t)m0*DDIM, DDIM, g_w + (size_t)n0*DDIM, DDIM, DDIM/64,
            aoff, boff);
    __syncthreads();

    // stage tile (+bias) to smem [128][132] fp32
    float* smC = (float*)sm;
    #pragma unroll
    for (int ni = 0; ni < 8; ni++){
        const int c = wn*64 + ni*8 + 2*ft;
        const float b0 = bias[n0 + c], b1 = bias[n0 + c + 1];
        #pragma unroll
        for (int mi = 0; mi < 4; mi++){
            const int rr = wm*64 + 16*mi + fg;
            smC[rr*132 + c]     = acc[mi][ni][0] + b0;
            smC[rr*132 + c + 1] = acc[mi][ni][1] + b1;
            smC[(rr+8)*132 + c]     = acc[mi][ni][2] + b0;
            smC[(rr+8)*132 + c + 1] = acc[mi][ni][3] + b1;
        }
    }
    __syncthreads();

    const int s = n0 >> 11, h = (n0 & 2047) >> 7;
    const int bb = m0 >> 11, t0 = m0 & 2047;
    if (s < 2){
        // RoPE: each thread owns one row (pairs c, c+64), write fp16
        const int r = tid;
        const int t = t0 + r;
        __half* dst = (s ? g_k : g_q) + ((size_t)(bb*NH + h)*TT + t)*HD;
        const float* csr = cs + (size_t)t*HD;
        const float* snr = sn + (size_t)t*HD;
        #pragma unroll
        for (int jj = 0; jj < 16; jj++){
            const int c = jj*4;
            float4 x1 = *(const float4*)(smC + r*132 + c);
            float4 x2 = *(const float4*)(smC + r*132 + c + 64);
            float4 c0 = *(const float4*)(csr + c);
            float4 s0 = *(const float4*)(snr + c);
            float4 c1 = *(const float4*)(csr + c + 64);
            float4 s1 = *(const float4*)(snr + c + 64);
            *(uint2*)(dst + c) = h4(x1.x*c0.x - x2.x*s0.x, x1.y*c0.y - x2.y*s0.y,
                                    x1.z*c0.z - x2.z*s0.z, x1.w*c0.w - x2.w*s0.w);
            *(uint2*)(dst + c + 64) = h4(x2.x*c1.x + x1.x*s1.x, x2.y*c1.y + x1.y*s1.y,
                                         x2.z*c1.z + x1.z*s1.z, x2.w*c1.w + x1.w*s1.w);
        }
    } else {
        __half* dstb = g_vt + (size_t)(bb*NH + h)*HD*TT;
        #pragma unroll
        for (int i = 0; i < 32; i++){
            const int ii = tid + i*128;
            const int d = ii >> 5, tq = ii & 31;
            *(uint2*)(dstb + (size_t)d*TT + t0 + tq*4) =
                h4(smC[(tq*4 + 0)*132 + d], smC[(tq*4 + 1)*132 + d],
                   smC[(tq*4 + 2)*132 + d], smC[(tq*4 + 3)*132 + d]);
        }
    }
}

// ======================= Flash attention (fp16 operands, fp32 softmax) =======================
__global__ __launch_bounds__(256, 1) void k_flash()
{
    extern __shared__ char sm[];
    const uint32_t smb = smem_u32(sm);
    const int tid = threadIdx.x;
    const int w = tid >> 5, l = tid & 31;
    const int wm = w >> 2, wn = w & 3;
    const int fg = l >> 2, ft = l & 3;
    const int mt = (TT/128 - 1) - blockIdx.x;
    const int bh = blockIdx.y;
    const int m0 = mt * 128;
    const int jmax = 2*mt + 1;

    const uint32_t Qs = smb + FOFF_Q;
    const uint32_t Ks = smb + FOFF_K;
    const uint32_t Vs = smb + FOFF_V;
    const uint32_t Ps = smb + FOFF_P;
    float* pmax = (float*)(sm + FOFF_PMAX);
    float* psum = (float*)(sm + FOFF_PSUM);
    float* smM  = (float*)(sm + FOFF_M);
    float* smL  = (float*)(sm + FOFF_L);

    const int aoff  = (wm*64 + (l&15))*FP + ((l>>4)<<4);
    const int boffS = (wn*16 + (l&15))*FP + ((l>>4)<<4);
    const int boffV = (wn*32 + (l&15))*FP + ((l>>4)<<4);

    if (tid < 128){ smM[tid] = -FLT_MAX; smL[tid] = 0.f; }

    float oacc[4][4][4];
    #pragma unroll
    for (int mi = 0; mi < 4; mi++)
        #pragma unroll
        for (int ni = 0; ni < 4; ni++)
            #pragma unroll
            for (int j = 0; j < 4; j++) oacc[mi][ni][j] = 0.f;

    const __half* Qg = g_q + ((size_t)bh*TT + m0)*HD;
    const __half* Kg = g_k + (size_t)bh*TT*HD;
    const __half* Vg = g_vt + (size_t)bh*HD*TT;

    // K tile: 64 rows x 2 d-chunks (1024 cp16)
    auto loadK = [&](uint32_t dst, int t0){
        #pragma unroll
        for (int i = 0; i < 4; i++){
            const int idx = tid + i*256;
            const int c = idx >> 9, r = (idx >> 3) & 63, kc = idx & 7;
            cp16(dst + c*KCH + r*FP + kc*16, Kg + (size_t)(t0 + r)*HD + c*64 + kc*8);
        }
    };
    // V tile: 128 d-rows x 64 t halves (1024 cp16)
    auto loadV = [&](int t0){
        #pragma unroll
        for (int i = 0; i < 4; i++){
            const int idx = tid + i*256;
            const int d = (idx >> 3) & 127, kc = idx & 7;
            cp16(Vs + d*FP + kc*16, Vg + (size_t)d*TT + t0 + kc*8);
        }
    };

    // prologue: Q (2 chunks, 2048 cp16) + K(0); then K(1)
    #pragma unroll
    for (int i = 0; i < 8; i++){
        const int idx = tid + i*256;
        const int c = idx >> 10, r = (idx >> 3) & 127, kc = idx & 7;
        cp16(Qs + c*QCH + r*FP + kc*16, Qg + (size_t)r*HD + c*64 + kc*8);
    }
    loadK(Ks, 0);
    CP_COMMIT();
    if (jmax >= 1) loadK(Ks + KTILE, 64);
    CP_COMMIT();

    for (int jt = 0; jt <= jmax; jt++){
        loadV(jt*64);
        CP_COMMIT();
        CP_WAIT2();
        __syncthreads();

        const uint32_t Kb = Ks + (jt & 1)*KTILE;

        // ---- S = Q·K^T (warp 64x16, d=128 over 8 k16 slices) ----
        float sacc[4][2][4];
        #pragma unroll
        for (int mi = 0; mi < 4; mi++)
            #pragma unroll
            for (int ni = 0; ni < 2; ni++)
                #pragma unroll
                for (int j = 0; j < 4; j++) sacc[mi][ni][j] = 0.f;
        #pragma unroll
        for (int ks = 0; ks < 8; ks++){
            uint32_t a[4][4], b[4];
            #pragma unroll
            for (int mi = 0; mi < 4; mi++)
                LDMX4(a[mi], Qs + (ks>>2)*QCH + aoff + mi*(16*FP) + (ks&3)*32);
            LDMX4(b, Kb + (ks>>2)*KCH + boffS + (ks&3)*32);
            #pragma unroll
            for (int mi = 0; mi < 4; mi++){
                mma16(sacc[mi][0], a[mi], b[0], b[2]);
                mma16(sacc[mi][1], a[mi], b[1], b[3]);
            }
        }

        // ---- scale + causal mask + per-warp row max ----
        const int coff = jt*64 - m0;
        float tm[4][2];
        #pragma unroll
        for (int mi = 0; mi < 4; mi++){ tm[mi][0] = -FLT_MAX; tm[mi][1] = -FLT_MAX; }
        #pragma unroll
        for (int mi = 0; mi < 4; mi++)
            #pragma unroll
            for (int ni = 0; ni < 2; ni++)
                #pragma unroll
                for (int j = 0; j < 4; j++){
                    float v = sacc[mi][ni][j] * SCALE;
                    if (coff >= 0){
                        const int cl = wn*16 + ni*8 + 2*ft + (j & 1);
                        const int rl = wm*64 + mi*16 + fg + 8*(j >> 1);
                        if (coff + cl > rl) v = -FLT_MAX;
                    }
                    sacc[mi][ni][j] = v;
                    tm[mi][j >> 1] = fmaxf(tm[mi][j >> 1], v);
                }
        #pragma unroll
        for (int mi = 0; mi < 4; mi++)
            #pragma unroll
            for (int hi = 0; hi < 2; hi++){
                tm[mi][hi] = fmaxf(tm[mi][hi], __shfl_xor_sync(0xffffffffu, tm[mi][hi], 1));
                tm[mi][hi] = fmaxf(tm[mi][hi], __shfl_xor_sync(0xffffffffu, tm[mi][hi], 2));
            }
        if (ft == 0){
            #pragma unroll
            for (int mi = 0; mi < 4; mi++)
                #pragma unroll
                for (int hi = 0; hi < 2; hi++)
                    pmax[(wm*64 + mi*16 + fg + 8*hi)*4 + wn] = tm[mi][hi];
        }
        __syncthreads();                        // [A]

        if (jt + 2 <= jmax) loadK(Ks + (jt & 1)*KTILE, (jt + 2)*64);
        CP_COMMIT();

        // ---- m_new, factor, P=exp, row sums ----
        float mnew[4][2], fct[4][2];
        #pragma unroll
        for (int mi = 0; mi < 4; mi++)
            #pragma unroll
            for (int hi = 0; hi < 2; hi++){
                const int r = wm*64 + mi*16 + fg + 8*hi;
                const float mo = smM[r];
                const float mx = fmaxf(fmaxf(pmax[r*4+0], pmax[r*4+1]),
                                       fmaxf(pmax[r*4+2], pmax[r*4+3]));
                const float mn = fmaxf(mo, mx);
                mnew[mi][hi] = mn;
                fct[mi][hi] = __expf(mo - mn);
            }
        float rs[4][2];
        #pragma unroll
        for (int mi = 0; mi < 4; mi++){ rs[mi][0] = 0.f; rs[mi][1] = 0.f; }
        #pragma unroll
        for (int mi = 0; mi < 4; mi++)
            #pragma unroll
            for (int ni = 0; ni < 2; ni++)
                #pragma unroll
                for (int j = 0; j < 4; j++){
                    const int hi = j >> 1;
                    const float p = __expf(sacc[mi][ni][j] - mnew[mi][hi]);
                    sacc[mi][ni][j] = p;
                    rs[mi][hi] += p;
                }
        #pragma unroll
        for (int mi = 0; mi < 4; mi++)
            #pragma unroll
            for (int hi = 0; hi < 2; hi++){
                rs[mi][hi] += __shfl_xor_sync(0xffffffffu, rs[mi][hi], 1);
                rs[mi][hi] += __shfl_xor_sync(0xffffffffu, rs[mi][hi], 2);
            }
        if (ft == 0){
            #pragma unroll
            for (int mi = 0; mi < 4; mi++)
                #pragma unroll
                for (int hi = 0; hi < 2; hi++)
                    psum[(wm*64 + mi*16 + fg + 8*hi)*4 + wn] = rs[mi][hi];
        }
        // rescale O
        #pragma unroll
        for (int mi = 0; mi < 4; mi++)
            #pragma unroll
            for (int ni = 0; ni < 4; ni++)
                #pragma unroll
                for (int j = 0; j < 4; j++)
                    oacc[mi][ni][j] *= fct[mi][j >> 1];
        // stage P (fp16)
        #pragma unroll
        for (int mi = 0; mi < 4; mi++)
            #pragma unroll
            for (int ni = 0; ni < 2; ni++){
                const int r0 = wm*64 + 16*mi + fg;
                const int cl = wn*16 + ni*8 + 2*ft;
                __half2 lo = __floats2half2_rn(sacc[mi][ni][0], sacc[mi][ni][1]);
                __half2 hi2 = __floats2half2_rn(sacc[mi][ni][2], sacc[mi][ni][3]);
                *(__half2*)(sm + FOFF_P + (size_t)r0*FP + cl*2) = lo;
                *(__half2*)(sm + FOFF_P + (size_t)(r0+8)*FP + cl*2) = hi2;
            }
        CP_WAIT1();
        __syncthreads();                        // [B]

        if (wn == 0 && ft == 0){
            #pragma unroll
            for (int mi = 0; mi < 4; mi++)
                #pragma unroll
                for (int hi = 0; hi < 2; hi++){
                    const int r = wm*64 + mi*16 + fg + 8*hi;
                    smL[r] = smL[r]*fct[mi][hi]
                           + (psum[r*4+0] + psum[r*4+1] + psum[r*4+2] + psum[r*4+3]);
                    smM[r] = mnew[mi][hi];
                }
        }

        // ---- O += P·V (warp 64x32 of d, k=64 t over 4 k16 slices) ----
        #pragma unroll
        for (int ks = 0; ks < 4; ks++){
            uint32_t a[4][4], b[2][4];
            #pragma unroll
            for (int mi = 0; mi < 4; mi++)
                LDMX4(a[mi], Ps + aoff + mi*(16*FP) + ks*32);
            #pragma unroll
            for (int p = 0; p < 2; p++)
                LDMX4(b[p], Vs + boffV + p*(16*FP) + ks*32);
            #pragma unroll
            for (int mi = 0; mi < 4; mi++)
                #pragma unroll
                for (int p = 0; p < 2; p++){
                    mma16(oacc[mi][2*p],   a[mi], b[p][0], b[p][2]);
                    mma16(oacc[mi][2*p+1], a[mi], b[p][1], b[p][3]);
                }
        }
        __syncthreads();                        // [C]
    }

    // ---- normalize + write O (fp16) ----
    const int bb = bh >> 4, h = bh & 15;
    #pragma unroll
    for (int mi = 0; mi < 4; mi++){
        #pragma unroll
        for (int hi = 0; hi < 2; hi++){
            const int r = wm*64 + mi*16 + fg + 8*hi;
            const float inv = 1.f / smL[r];
            __half* dst = g_attn + ((size_t)(bb*TT + m0 + r))*DDIM + h*HD;
            #pragma unroll
            for (int ni = 0; ni < 4; ni++){
                const int c = wn*32 + ni*8 + 2*ft;
                *(__half2*)(dst + c) = __floats2half2_rn(oacc[mi][ni][2*hi]*inv,
                                                         oacc[mi][ni][2*hi+1]*inv);
            }
        }
    }
}

// ======================= Output projection =======================
__global__ __launch_bounds__(128, 2) void k_out(const float* __restrict__ bias,
                                                float* __restrict__ Cout)
{
    GEMM_PROLOGUE();
    const int n0 = blockIdx.x * 128, m0 = blockIdx.y * 128;
    gemm_cp(smb, acc, g_attn + (size_t)m0*DDIM, DDIM, g_wo + (size_t)n0*DDIM, DDIM,
            DDIM/64, aoff, boff);
    #pragma unroll
    for (int ni = 0; ni < 8; ni++){
        const int c = n0 + wn*64 + ni*8 + 2*ft;
        const float b0 = bias[c], b1 = bias[c + 1];
        #pragma unroll
        for (int mi = 0; mi < 4; mi++){
            const int m = m0 + 64*wm + 16*mi + fg;
            *(float2*)(Cout + (size_t)m*DDIM + c)     = make_float2(acc[mi][ni][0] + b0, acc[mi][ni][1] + b1);
            *(float2*)(Cout + (size_t)(m+8)*DDIM + c) = make_float2(acc[mi][ni][2] + b0, acc[mi][ni][3] + b1);
        }
    }
}

// ======================= launch =======================
extern "C" void kernel_launch(void* const* d_in, const int* in_sizes, int n_in,
                              void* d_out, int out_size)
{
    (void)in_sizes; (void)n_in; (void)out_size;
    const float* x      = (const float*)d_in[0];
    const float* rc     = (const float*)d_in[1];
    const float* rs     = (const float*)d_in[2];
    const float* qkv_w  = (const float*)d_in[3];
    const float* qkv_b  = (const float*)d_in[4];
    const float* out_w  = (const float*)d_in[5];
    const float* out_b  = (const float*)d_in[6];
    float* out = (float*)d_out;

    cudaFuncSetAttribute(k_qkv,   cudaFuncAttributeMaxDynamicSharedMemorySize, SMEM_ALL);
    cudaFuncSetAttribute(k_flash, cudaFuncAttributeMaxDynamicSharedMemorySize, FSMEM);
    cudaFuncSetAttribute(k_out,   cudaFuncAttributeMaxDynamicSharedMemorySize, SMEM_ALL);

    __half *px, *pw, *pwo;
    cudaGetSymbolAddress((void**)&px,  g_x);
    cudaGetSymbolAddress((void**)&pw,  g_w);
    cudaGetSymbolAddress((void**)&pwo, g_wo);

    k_half<<<2048, 256>>>((const float4*)x,     (uint2*)px,  MROWS*DDIM/4);
    k_half<<<3072, 256>>>((const float4*)qkv_w, (uint2*)pw,  E3*DDIM/4);
    k_half<<<1024, 256>>>((const float4*)out_w, (uint2*)pwo, DDIM*DDIM/4);

    k_qkv<<<dim3(E3/128, MROWS/128), 128, SMEM_ALL>>>(qkv_b, rc, rs);
    k_flash<<<dim3(TT/128, BH), 256, FSMEM>>>();
    k_out<<<dim3(DDIM/128, MROWS/128), 128, SMEM_ALL>>>(out_b, out);
}

// round 17
// speedup vs baseline: 2.6734x; 1.0060x over previous
#include <cuda_runtime.h>
#include <cuda_fp16.h>
#include <cstdint>
#include <math.h>
#include <float.h>

#define BD 2
#define TT 2048
#define DDIM 2048
#define NH 16
#define HD 128
#define BH (BD*NH)         // 32
#define MROWS (BD*TT)      // 4096
#define E3 (3*DDIM)        // 6144
#define SCALE 0.08838834764831843f

// Projection GEMMs: CTA 128x128, 256 thr (8 warps 2x4), warp tile 64x32.
// fp16 m16n8k16; K-chunk 64 halves (128B rows), pitch 144B; 3-stage cp.async.
#define P32 144
#define ASZ32 (128*P32)        // 18432
#define STG32 (2*ASZ32)        // 36864
#define SMEM_ALL (3*STG32)     // 110592 (covers 67584B qkv epilogue staging)

// ---- Flash geometry (fp16, unchanged from R16): BM=128, BN=64 ----
#define FP   144
#define QCH  (128*FP)
#define KCH  (64*FP)
#define KTILE (2*KCH)
#define VTILE (128*FP)
#define PTILE (128*FP)
#define FOFF_Q 0
#define FOFF_K (2*QCH)
#define FOFF_V (FOFF_K + 2*KTILE)
#define FOFF_P (FOFF_V + VTILE)
#define FOFF_PMAX (FOFF_P + PTILE)
#define FOFF_PSUM (FOFF_PMAX + 2048)
#define FOFF_M    (FOFF_PSUM + 2048)
#define FOFF_L    (FOFF_M + 512)
#define FSMEM     (FOFF_L + 512)       // 115712

// ------------------ scratch (static device, allocation-free) ------------------
__device__ __half g_x [(size_t)MROWS*DDIM];
__device__ __half g_w [(size_t)E3*DDIM];
__device__ __half g_wo[(size_t)DDIM*DDIM];
__device__ __half g_q [(size_t)BH*TT*HD];
__device__ __half g_k [(size_t)BH*TT*HD];
__device__ __half g_vt[(size_t)BH*HD*TT];     // V transposed [bh][d][t]
__device__ __half g_attn[(size_t)MROWS*DDIM];

// ------------------ helpers ------------------
static __device__ __forceinline__ uint32_t smem_u32(const void* p){
    uint32_t a;
    asm("{ .reg .u64 t; cvta.to.shared.u64 t, %1; cvt.u32.u64 %0, t; }" : "=r"(a) : "l"(p));
    return a;
}
static __device__ __forceinline__ uint2 h4(float a, float b, float c, float d){
    __half2 lo = __floats2half2_rn(a, b), hi = __floats2half2_rn(c, d);
    uint2 u; u.x = *(uint32_t*)&lo; u.y = *(uint32_t*)&hi; return u;
}

static __device__ __forceinline__ void cp16(uint32_t dst, const void* src){
    uint64_t g;
    asm("cvta.to.global.u64 %0, %1;" : "=l"(g) : "l"(src));
    asm volatile("cp.async.cg.shared.global [%0], [%1], 16;" :: "r"(dst), "l"(g) : "memory");
}
#define CP_COMMIT() asm volatile("cp.async.commit_group;" ::: "memory")
#define CP_WAIT1()  asm volatile("cp.async.wait_group 1;" ::: "memory")
#define CP_WAIT2()  asm volatile("cp.async.wait_group 2;" ::: "memory")

#define LDMX4(r, addr) asm volatile( \
    "ldmatrix.sync.aligned.m8n8.x4.shared.b16 {%0,%1,%2,%3}, [%4];" \
    : "=r"((r)[0]),"=r"((r)[1]),"=r"((r)[2]),"=r"((r)[3]) : "r"(addr))

// fp16 m16n8k16, fp32 accum
static __device__ __forceinline__ void mma16(float* c, const uint32_t* a,
                                             uint32_t b0, uint32_t b1){
    asm volatile(
        "mma.sync.aligned.m16n8k16.row.col.f32.f16.f16.f32 "
        "{%0,%1,%2,%3}, {%4,%5,%6,%7}, {%8,%9}, {%0,%1,%2,%3};"
        : "+f"(c[0]), "+f"(c[1]), "+f"(c[2]), "+f"(c[3])
        : "r"(a[0]), "r"(a[1]), "r"(a[2]), "r"(a[3]), "r"(b0), "r"(b1));
}

// compute one K=64 chunk: warp tile 64x32, 4 k16 slices, 16 MMAs each
static __device__ __forceinline__ void compute64(uint32_t stg, float (&acc)[4][4][4],
                                                 int aoff, int boff)
{
    #pragma unroll
    for (int ks = 0; ks < 4; ks++){
        uint32_t a[4][4], b[2][4];
        #pragma unroll
        for (int mi = 0; mi < 4; mi++)
            LDMX4(a[mi], stg + aoff + mi*(16*P32) + ks*32);
        #pragma unroll
        for (int p = 0; p < 2; p++)
            LDMX4(b[p], stg + ASZ32 + boff + p*(16*P32) + ks*32);
        #pragma unroll
        for (int mi = 0; mi < 4; mi++)
            #pragma unroll
            for (int p = 0; p < 2; p++){
                mma16(acc[mi][2*p],   a[mi], b[p][0], b[p][2]);
                mma16(acc[mi][2*p+1], a[mi], b[p][1], b[p][3]);
            }
    }
}

// cp.async loads for one K=64-half chunk (A,B: 128 rows x 128B; 256 threads)
static __device__ __forceinline__ void cp_issue64(uint32_t stg,
    const __half* __restrict__ A, size_t lda,
    const __half* __restrict__ B, size_t ldb, int k0, int tid)
{
    const int kc = tid & 7, r0 = tid >> 3;   // 32 row-groups of 4
    #pragma unroll
    for (int j = 0; j < 4; j++){
        const int r = r0 + 32*j;
        cp16(stg + r*P32 + kc*16, A + (size_t)r*lda + k0 + kc*8);
    }
    #pragma unroll
    for (int j = 0; j < 4; j++){
        const int r = r0 + 32*j;
        cp16(stg + ASZ32 + r*P32 + kc*16, B + (size_t)r*ldb + k0 + kc*8);
    }
}

// C[128,128] += A[128,K]*B[128,K]^T (fp16), K = nIter*64, 3-stage pipeline
static __device__ __forceinline__ void gemm_cp(uint32_t smb, float (&acc)[4][4][4],
    const __half* __restrict__ A, size_t lda,
    const __half* __restrict__ B, size_t ldb, int nIter, int aoff, int boff)
{
    const int tid = threadIdx.x;
    #pragma unroll
    for (int s = 0; s < 2; s++){
        if (s < nIter) cp_issue64(smb + s*STG32, A, lda, B, ldb, s*64, tid);
        CP_COMMIT();
    }
    int stq = 2;
    for (int kt = 0; kt < nIter; kt++){
        CP_WAIT1();
        __syncthreads();
        if (kt + 2 < nIter){
            cp_issue64(smb + stq*STG32, A, lda, B, ldb, (kt+2)*64, tid);
            if (++stq == 3) stq = 0;
        }
        CP_COMMIT();
        compute64(smb + (kt % 3)*STG32, acc, aoff, boff);
    }
}

#define GEMM_PROLOGUE() \
    extern __shared__ char sm[]; \
    const uint32_t smb = smem_u32(sm); \
    const int tid = threadIdx.x; \
    const int w = tid >> 5, wm = w >> 2, wn = w & 3, l = tid & 31; \
    const int fg = l >> 2, ft = l & 3; \
    const int aoff = (wm*64 + (l&15))*P32 + ((l>>4)<<4); \
    const int boff = (wn*32 + (l&15))*P32 + ((l>>4)<<4); \
    float acc[4][4][4]; \
    _Pragma("unroll") for (int mi = 0; mi < 4; mi++) \
    _Pragma("unroll") for (int ni = 0; ni < 4; ni++) \
    _Pragma("unroll") for (int j = 0; j < 4; j++) acc[mi][ni][j] = 0.f;

// ======================= convert fp32 inputs to fp16 =======================
__global__ void k_half(const float4* __restrict__ src, uint2* __restrict__ dst, int n4)
{
    for (int i = blockIdx.x*blockDim.x + threadIdx.x; i < n4; i += gridDim.x*blockDim.x){
        float4 v = src[i];
        dst[i] = h4(v.x, v.y, v.z, v.w);
    }
}

// ======================= QKV GEMM + fused bias/RoPE + V transpose =======================
__global__ __launch_bounds__(256, 2) void k_qkv(const float* __restrict__ bias,
                                                const float* __restrict__ cs,
                                                const float* __restrict__ sn)
{
    GEMM_PROLOGUE();
    const int n0 = blockIdx.x * 128, m0 = blockIdx.y * 128;
    gemm_cp(smb, acc, g_x + (size_t)m0*DDIM, DDIM, g_w + (size_t)n0*DDIM, DDIM, DDIM/64,
            aoff, boff);
    __syncthreads();

    // stage tile (+bias) to smem [128][132] fp32
    float* smC = (float*)sm;
    #pragma unroll
    for (int ni = 0; ni < 4; ni++){
        const int c = wn*32 + ni*8 + 2*ft;
        const float b0 = bias[n0 + c], b1 = bias[n0 + c + 1];
        #pragma unroll
        for (int mi = 0; mi < 4; mi++){
            const int rr = wm*64 + 16*mi + fg;
            smC[rr*132 + c]     = acc[mi][ni][0] + b0;
            smC[rr*132 + c + 1] = acc[mi][ni][1] + b1;
            smC[(rr+8)*132 + c]     = acc[mi][ni][2] + b0;
            smC[(rr+8)*132 + c + 1] = acc[mi][ni][3] + b1;
        }
    }
    __syncthreads();

    const int s = n0 >> 11, h = (n0 & 2047) >> 7;
    const int bb = m0 >> 11, t0 = m0 & 2047;
    if (s < 2){
        // RoPE: r = tid&127 owns row, half = tid>>7 owns 32 of 64 column-pairs
        const int r = tid & 127, half = tid >> 7;
        const int t = t0 + r;
        __half* dst = (s ? g_k : g_q) + ((size_t)(bb*NH + h)*TT + t)*HD;
        const float* csr = cs + (size_t)t*HD;
        const float* snr = sn + (size_t)t*HD;
        #pragma unroll
        for (int jj = 0; jj < 8; jj++){
            const int c = half*32 + jj*4;
            float4 x1 = *(const float4*)(smC + r*132 + c);
            float4 x2 = *(const float4*)(smC + r*132 + c + 64);
            float4 c0 = *(const float4*)(csr + c);
            float4 s0 = *(const float4*)(snr + c);
            float4 c1 = *(const float4*)(csr + c + 64);
            float4 s1 = *(const float4*)(snr + c + 64);
            *(uint2*)(dst + c) = h4(x1.x*c0.x - x2.x*s0.x, x1.y*c0.y - x2.y*s0.y,
                                    x1.z*c0.z - x2.z*s0.z, x1.w*c0.w - x2.w*s0.w);
            *(uint2*)(dst + c + 64) = h4(x2.x*c1.x + x1.x*s1.x, x2.y*c1.y + x1.y*s1.y,
                                         x2.z*c1.z + x1.z*s1.z, x2.w*c1.w + x1.w*s1.w);
        }
    } else {
        __half* dstb = g_vt + (size_t)(bb*NH + h)*HD*TT;
        #pragma unroll
        for (int i = 0; i < 16; i++){
            const int ii = tid + i*256;
            const int d = ii >> 5, tq = ii & 31;
            *(uint2*)(dstb + (size_t)d*TT + t0 + tq*4) =
                h4(smC[(tq*4 + 0)*132 + d], smC[(tq*4 + 1)*132 + d],
                   smC[(tq*4 + 2)*132 + d], smC[(tq*4 + 3)*132 + d]);
        }
    }
}

// ======================= Flash attention (unchanged from R16) =======================
__global__ __launch_bounds__(256, 1) void k_flash()
{
    extern __shared__ char sm[];
    const uint32_t smb = smem_u32(sm);
    const int tid = threadIdx.x;
    const int w = tid >> 5, l = tid & 31;
    const int wm = w >> 2, wn = w & 3;
    const int fg = l >> 2, ft = l & 3;
    const int mt = (TT/128 - 1) - blockIdx.x;
    const int bh = blockIdx.y;
    const int m0 = mt * 128;
    const int jmax = 2*mt + 1;

    const uint32_t Qs = smb + FOFF_Q;
    const uint32_t Ks = smb + FOFF_K;
    const uint32_t Vs = smb + FOFF_V;
    const uint32_t Ps = smb + FOFF_P;
    float* pmax = (float*)(sm + FOFF_PMAX);
    float* psum = (float*)(sm + FOFF_PSUM);
    float* smM  = (float*)(sm + FOFF_M);
    float* smL  = (float*)(sm + FOFF_L);

    const int aoff  = (wm*64 + (l&15))*FP + ((l>>4)<<4);
    const int boffS = (wn*16 + (l&15))*FP + ((l>>4)<<4);
    const int boffV = (wn*32 + (l&15))*FP + ((l>>4)<<4);

    if (tid < 128){ smM[tid] = -FLT_MAX; smL[tid] = 0.f; }

    float oacc[4][4][4];
    #pragma unroll
    for (int mi = 0; mi < 4; mi++)
        #pragma unroll
        for (int ni = 0; ni < 4; ni++)
            #pragma unroll
            for (int j = 0; j < 4; j++) oacc[mi][ni][j] = 0.f;

    const __half* Qg = g_q + ((size_t)bh*TT + m0)*HD;
    const __half* Kg = g_k + (size_t)bh*TT*HD;
    const __half* Vg = g_vt + (size_t)bh*HD*TT;

    auto loadK = [&](uint32_t dst, int t0){
        #pragma unroll
        for (int i = 0; i < 4; i++){
            const int idx = tid + i*256;
            const int c = idx >> 9, r = (idx >> 3) & 63, kc = idx & 7;
            cp16(dst + c*KCH + r*FP + kc*16, Kg + (size_t)(t0 + r)*HD + c*64 + kc*8);
        }
    };
    auto loadV = [&](int t0){
        #pragma unroll
        for (int i = 0; i < 4; i++){
            const int idx = tid + i*256;
            const int d = (idx >> 3) & 127, kc = idx & 7;
            cp16(Vs + d*FP + kc*16, Vg + (size_t)d*TT + t0 + kc*8);
        }
    };

    #pragma unroll
    for (int i = 0; i < 8; i++){
        const int idx = tid + i*256;
        const int c = idx >> 10, r = (idx >> 3) & 127, kc = idx & 7;
        cp16(Qs + c*QCH + r*FP + kc*16, Qg + (size_t)r*HD + c*64 + kc*8);
    }
    loadK(Ks, 0);
    CP_COMMIT();
    if (jmax >= 1) loadK(Ks + KTILE, 64);
    CP_COMMIT();

    for (int jt = 0; jt <= jmax; jt++){
        loadV(jt*64);
        CP_COMMIT();
        CP_WAIT2();
        __syncthreads();

        const uint32_t Kb = Ks + (jt & 1)*KTILE;

        float sacc[4][2][4];
        #pragma unroll
        for (int mi = 0; mi < 4; mi++)
            #pragma unroll
            for (int ni = 0; ni < 2; ni++)
                #pragma unroll
                for (int j = 0; j < 4; j++) sacc[mi][ni][j] = 0.f;
        #pragma unroll
        for (int ks = 0; ks < 8; ks++){
            uint32_t a[4][4], b[4];
            #pragma unroll
            for (int mi = 0; mi < 4; mi++)
                LDMX4(a[mi], Qs + (ks>>2)*QCH + aoff + mi*(16*FP) + (ks&3)*32);
            LDMX4(b, Kb + (ks>>2)*KCH + boffS + (ks&3)*32);
            #pragma unroll
            for (int mi = 0; mi < 4; mi++){
                mma16(sacc[mi][0], a[mi], b[0], b[2]);
                mma16(sacc[mi][1], a[mi], b[1], b[3]);
            }
        }

        const int coff = jt*64 - m0;
        float tm[4][2];
        #pragma unroll
        for (int mi = 0; mi < 4; mi++){ tm[mi][0] = -FLT_MAX; tm[mi][1] = -FLT_MAX; }
        #pragma unroll
        for (int mi = 0; mi < 4; mi++)
            #pragma unroll
            for (int ni = 0; ni < 2; ni++)
                #pragma unroll
                for (int j = 0; j < 4; j++){
                    float v = sacc[mi][ni][j] * SCALE;
                    if (coff >= 0){
                        const int cl = wn*16 + ni*8 + 2*ft + (j & 1);
                        const int rl = wm*64 + mi*16 + fg + 8*(j >> 1);
                        if (coff + cl > rl) v = -FLT_MAX;
                    }
                    sacc[mi][ni][j] = v;
                    tm[mi][j >> 1] = fmaxf(tm[mi][j >> 1], v);
                }
        #pragma unroll
        for (int mi = 0; mi < 4; mi++)
            #pragma unroll
            for (int hi = 0; hi < 2; hi++){
                tm[mi][hi] = fmaxf(tm[mi][hi], __shfl_xor_sync(0xffffffffu, tm[mi][hi], 1));
                tm[mi][hi] = fmaxf(tm[mi][hi], __shfl_xor_sync(0xffffffffu, tm[mi][hi], 2));
            }
        if (ft == 0){
            #pragma unroll
            for (int mi = 0; mi < 4; mi++)
                #pragma unroll
                for (int hi = 0; hi < 2; hi++)
                    pmax[(wm*64 + mi*16 + fg + 8*hi)*4 + wn] = tm[mi][hi];
        }
        __syncthreads();                        // [A]

        if (jt + 2 <= jmax) loadK(Ks + (jt & 1)*KTILE, (jt + 2)*64);
        CP_COMMIT();

        float mnew[4][2], fct[4][2];
        #pragma unroll
        for (int mi = 0; mi < 4; mi++)
            #pragma unroll
            for (int hi = 0; hi < 2; hi++){
                const int r = wm*64 + mi*16 + fg + 8*hi;
                const float mo = smM[r];
                const float mx = fmaxf(fmaxf(pmax[r*4+0], pmax[r*4+1]),
                                       fmaxf(pmax[r*4+2], pmax[r*4+3]));
                const float mn = fmaxf(mo, mx);
                mnew[mi][hi] = mn;
                fct[mi][hi] = __expf(mo - mn);
            }
        float rs[4][2];
        #pragma unroll
        for (int mi = 0; mi < 4; mi++){ rs[mi][0] = 0.f; rs[mi][1] = 0.f; }
        #pragma unroll
        for (int mi = 0; mi < 4; mi++)
            #pragma unroll
            for (int ni = 0; ni < 2; ni++)
                #pragma unroll
                for (int j = 0; j < 4; j++){
                    const int hi = j >> 1;
                    const float p = __expf(sacc[mi][ni][j] - mnew[mi][hi]);
                    sacc[mi][ni][j] = p;
                    rs[mi][hi] += p;
                }
        #pragma unroll
        for (int mi = 0; mi < 4; mi++)
            #pragma unroll
            for (int hi = 0; hi < 2; hi++){
                rs[mi][hi] += __shfl_xor_sync(0xffffffffu, rs[mi][hi], 1);
                rs[mi][hi] += __shfl_xor_sync(0xffffffffu, rs[mi][hi], 2);
            }
        if (ft == 0){
            #pragma unroll
            for (int mi = 0; mi < 4; mi++)
                #pragma unroll
                for (int hi = 0; hi < 2; hi++)
                    psum[(wm*64 + mi*16 + fg + 8*hi)*4 + wn] = rs[mi][hi];
        }
        #pragma unroll
        for (int mi = 0; mi < 4; mi++)
            #pragma unroll
            for (int ni = 0; ni < 4; ni++)
                #pragma unroll
                for (int j = 0; j < 4; j++)
                    oacc[mi][ni][j] *= fct[mi][j >> 1];
        #pragma unroll
        for (int mi = 0; mi < 4; mi++)
            #pragma unroll
            for (int ni = 0; ni < 2; ni++){
                const int r0 = wm*64 + 16*mi + fg;
                const int cl = wn*16 + ni*8 + 2*ft;
                __half2 lo = __floats2half2_rn(sacc[mi][ni][0], sacc[mi][ni][1]);
                __half2 hi2 = __floats2half2_rn(sacc[mi][ni][2], sacc[mi][ni][3]);
                *(__half2*)(sm + FOFF_P + (size_t)r0*FP + cl*2) = lo;
                *(__half2*)(sm + FOFF_P + (size_t)(r0+8)*FP + cl*2) = hi2;
            }
        CP_WAIT1();
        __syncthreads();                        // [B]

        if (wn == 0 && ft == 0){
            #pragma unroll
            for (int mi = 0; mi < 4; mi++)
                #pragma unroll
                for (int hi = 0; hi < 2; hi++){
                    const int r = wm*64 + mi*16 + fg + 8*hi;
                    smL[r] = smL[r]*fct[mi][hi]
                           + (psum[r*4+0] + psum[r*4+1] + psum[r*4+2] + psum[r*4+3]);
                    smM[r] = mnew[mi][hi];
                }
        }

        #pragma unroll
        for (int ks = 0; ks < 4; ks++){
            uint32_t a[4][4], b[2][4];
            #pragma unroll
            for (int mi = 0; mi < 4; mi++)
                LDMX4(a[mi], Ps + aoff + mi*(16*FP) + ks*32);
            #pragma unroll
            for (int p = 0; p < 2; p++)
                LDMX4(b[p], Vs + boffV + p*(16*FP) + ks*32);
            #pragma unroll
            for (int mi = 0; mi < 4; mi++)
                #pragma unroll
                for (int p = 0; p < 2; p++){
                    mma16(oacc[mi][2*p],   a[mi], b[p][0], b[p][2]);
                    mma16(oacc[mi][2*p+1], a[mi], b[p][1], b[p][3]);
                }
        }
        __syncthreads();                        // [C]
    }

    const int bb = bh >> 4, h = bh & 15;
    #pragma unroll
    for (int mi = 0; mi < 4; mi++){
        #pragma unroll
        for (int hi = 0; hi < 2; hi++){
            const int r = wm*64 + mi*16 + fg + 8*hi;
            const float inv = 1.f / smL[r];
            __half* dst = g_attn + ((size_t)(bb*TT + m0 + r))*DDIM + h*HD;
            #pragma unroll
            for (int ni = 0; ni < 4; ni++){
                const int c = wn*32 + ni*8 + 2*ft;
                *(__half2*)(dst + c) = __floats2half2_rn(oacc[mi][ni][2*hi]*inv,
                                                         oacc[mi][ni][2*hi+1]*inv);
            }
        }
    }
}

// ======================= Output projection =======================
__global__ __launch_bounds__(256, 2) void k_out(const float* __restrict__ bias,
                                                float* __restrict__ Cout)
{
    GEMM_PROLOGUE();
    const int n0 = blockIdx.x * 128, m0 = blockIdx.y * 128;
    gemm_cp(smb, acc, g_attn + (size_t)m0*DDIM, DDIM, g_wo + (size_t)n0*DDIM, DDIM,
            DDIM/64, aoff, boff);
    #pragma unroll
    for (int ni = 0; ni < 4; ni++){
        const int c = n0 + wn*32 + ni*8 + 2*ft;
        const float b0 = bias[c], b1 = bias[c + 1];
        #pragma unroll
        for (int mi = 0; mi < 4; mi++){
            const int m = m0 + 64*wm + 16*mi + fg;
            *(float2*)(Cout + (size_t)m*DDIM + c)     = make_float2(acc[mi][ni][0] + b0, acc[mi][ni][1] + b1);
            *(float2*)(Cout + (size_t)(m+8)*DDIM + c) = make_float2(acc[mi][ni][2] + b0, acc[mi][ni][3] + b1);
        }
    }
}

// ======================= launch =======================
extern "C" void kernel_launch(void* const* d_in, const int* in_sizes, int n_in,
                              void* d_out, int out_size)
{
    (void)in_sizes; (void)n_in; (void)out_size;
    const float* x      = (const float*)d_in[0];
    const float* rc     = (const float*)d_in[1];
    const float* rs     = (const float*)d_in[2];
    const float* qkv_w  = (const float*)d_in[3];
    const float* qkv_b  = (const float*)d_in[4];
    const float* out_w  = (const float*)d_in[5];
    const float* out_b  = (const float*)d_in[6];
    float* out = (float*)d_out;

    cudaFuncSetAttribute(k_qkv,   cudaFuncAttributeMaxDynamicSharedMemorySize, SMEM_ALL);
    cudaFuncSetAttribute(k_flash, cudaFuncAttributeMaxDynamicSharedMemorySize, FSMEM);
    cudaFuncSetAttribute(k_out,   cudaFuncAttributeMaxDynamicSharedMemorySize, SMEM_ALL);

    __half *px, *pw, *pwo;
    cudaGetSymbolAddress((void**)&px,  g_x);
    cudaGetSymbolAddress((void**)&pw,  g_w);
    cudaGetSymbolAddress((void**)&pwo, g_wo);

    k_half<<<2048, 256>>>((const float4*)x,     (uint2*)px,  MROWS*DDIM/4);
    k_half<<<3072, 256>>>((const float4*)qkv_w, (uint2*)pw,  E3*DDIM/4);
    k_half<<<1024, 256>>>((const float4*)out_w, (uint2*)pwo, DDIM*DDIM/4);

    k_qkv<<<dim3(E3/128, MROWS/128), 256, SMEM_ALL>>>(qkv_b, rc, rs);
    k_flash<<<dim3(TT/128, BH), 256, FSMEM>>>();
    k_out<<<dim3(DDIM/128, MROWS/128), 256, SMEM_ALL>>>(out_b, out);
}